// round 4
// baseline (speedup 1.0000x reference)
#include <cuda_runtime.h>
#include <cstdint>

#define N_NODES 100000
#define N_EDGES 1600000
#define E_TOTAL (N_EDGES + N_NODES)   // edges + self loops = 1,700,000

// ---------------------------------------------------------------------------
// Scratch (device globals -- no allocation allowed)
// ---------------------------------------------------------------------------
__device__ int   g_deg[N_NODES];
__device__ int   g_rowptr[N_NODES + 1];
__device__ int   g_cur[N_NODES];
__device__ int   g_col[E_TOTAL];
__device__ float g_dinv[N_NODES];
__device__ float g_bufA[(size_t)N_NODES * 64];
__device__ float g_bufB[(size_t)N_NODES * 64];
__device__ float g_bufC[(size_t)N_NODES * 64];
__device__ float g_bufD[(size_t)N_NODES * 64];
__device__ float g_as[(size_t)N_NODES * 4];
__device__ float g_ad[(size_t)N_NODES * 4];

__device__ __forceinline__ float lrelu(float x) { return x > 0.f ? x : 0.2f * x; }

// ---------------------------------------------------------------------------
// CSR build
// ---------------------------------------------------------------------------
__global__ void init_deg_kernel(int* deg, int n) {
    int i = blockIdx.x * blockDim.x + threadIdx.x;
    if (i < n) deg[i] = 1;  // self loop
}

__global__ void hist_kernel(const int* __restrict__ dst, int* __restrict__ deg, int e) {
    int i = blockIdx.x * blockDim.x + threadIdx.x;
    if (i < e) atomicAdd(&deg[dst[i]], 1);
}

// Single-block chunked Hillis-Steele exclusive scan (N=100K -> 98 chunks)
__global__ void scan_kernel(const int* __restrict__ deg, int* __restrict__ rowptr, int n) {
    __shared__ int sh[1024];
    __shared__ int soff;
    int tid = threadIdx.x;
    if (tid == 0) soff = 0;
    __syncthreads();
    for (int base = 0; base < n; base += 1024) {
        int v = (base + tid < n) ? deg[base + tid] : 0;
        sh[tid] = v;
        __syncthreads();
        for (int o = 1; o < 1024; o <<= 1) {
            int t = (tid >= o) ? sh[tid - o] : 0;
            __syncthreads();
            sh[tid] += t;
            __syncthreads();
        }
        int off = soff;
        if (base + tid < n) rowptr[base + tid] = off + sh[tid] - v;
        int ctot = sh[1023];
        __syncthreads();
        if (tid == 0) soff = off + ctot;
        __syncthreads();
    }
    if (tid == 0) rowptr[n] = soff;
}

__global__ void csr_init_kernel(const int* __restrict__ rowptr, const int* __restrict__ deg,
                                int* __restrict__ cur, int* __restrict__ col,
                                float* __restrict__ dinv, int n) {
    int i = blockIdx.x * blockDim.x + threadIdx.x;
    if (i >= n) return;
    int r = rowptr[i];
    col[r] = i;          // self loop in slot 0
    cur[i] = r + 1;
    dinv[i] = rsqrtf((float)deg[i]);
}

__global__ void fill_kernel(const int* __restrict__ src, const int* __restrict__ dst,
                            int* __restrict__ cur, int* __restrict__ col, int e) {
    int i = blockIdx.x * blockDim.x + threadIdx.x;
    if (i >= e) return;
    int p = atomicAdd(&cur[dst[i]], 1);
    col[p] = src[i];
}

// ---------------------------------------------------------------------------
// Dense GEMM: out[N,COUT] = (in[N,CIN] @ W) * (SCALE ? dinv[n] : 1)
// warp-per-node, W staged in SMEM
// ---------------------------------------------------------------------------
template <int CIN, int COUT, bool SCALE>
__global__ void gemm_kernel(const float* __restrict__ in, const float* __restrict__ W,
                            const float* __restrict__ dinv, float* __restrict__ out, int n_nodes) {
    __shared__ float Wsh[CIN * COUT];
    int tid = threadIdx.x;
    for (int i = tid; i < CIN * COUT; i += blockDim.x) Wsh[i] = W[i];
    __syncthreads();
    int warp = tid >> 5, lane = tid & 31;
    int n = blockIdx.x * (blockDim.x >> 5) + warp;
    if (n >= n_nodes) return;
    const float4* xr = reinterpret_cast<const float4*>(in + (size_t)n * CIN);
    if (COUT == 32) {
        float acc = 0.f;
#pragma unroll
        for (int k4 = 0; k4 < CIN / 4; k4++) {
            float4 x4 = __ldg(xr + k4);
            acc += x4.x * Wsh[(4 * k4 + 0) * COUT + lane];
            acc += x4.y * Wsh[(4 * k4 + 1) * COUT + lane];
            acc += x4.z * Wsh[(4 * k4 + 2) * COUT + lane];
            acc += x4.w * Wsh[(4 * k4 + 3) * COUT + lane];
        }
        if (SCALE) acc *= dinv[n];
        out[(size_t)n * COUT + lane] = acc;
    } else {
        float ax = 0.f, ay = 0.f;
#pragma unroll
        for (int k4 = 0; k4 < CIN / 4; k4++) {
            float4 x4 = __ldg(xr + k4);
            float xs0 = x4.x, xs1 = x4.y, xs2 = x4.z, xs3 = x4.w;
            float2 w;
            w = *reinterpret_cast<const float2*>(&Wsh[(4 * k4 + 0) * COUT + 2 * lane]);
            ax += xs0 * w.x; ay += xs0 * w.y;
            w = *reinterpret_cast<const float2*>(&Wsh[(4 * k4 + 1) * COUT + 2 * lane]);
            ax += xs1 * w.x; ay += xs1 * w.y;
            w = *reinterpret_cast<const float2*>(&Wsh[(4 * k4 + 2) * COUT + 2 * lane]);
            ax += xs2 * w.x; ay += xs2 * w.y;
            w = *reinterpret_cast<const float2*>(&Wsh[(4 * k4 + 3) * COUT + 2 * lane]);
            ax += xs3 * w.x; ay += xs3 * w.y;
        }
        if (SCALE) { float s = dinv[n]; ax *= s; ay *= s; }
        float2 r; r.x = ax; r.y = ay;
        *reinterpret_cast<float2*>(&out[(size_t)n * COUT + 2 * lane]) = r;
    }
}

// ---------------------------------------------------------------------------
// GCN aggregation: out[n] = relu(dinv[n]*sum_{s in N(n)} t[s] + bias) (+resid)
// warp-per-node, gather-only (t already pre-scaled by dinv[s])
// ---------------------------------------------------------------------------
template <int C, bool RESID>
__global__ void gcn_agg_kernel(const float* __restrict__ t, const int* __restrict__ rowptr,
                               const int* __restrict__ col, const float* __restrict__ dinv,
                               const float* __restrict__ bias, const float* __restrict__ resid,
                               float* __restrict__ out, int n_nodes) {
    int warp = (blockIdx.x * blockDim.x + threadIdx.x) >> 5;
    int lane = threadIdx.x & 31;
    if (warp >= n_nodes) return;
    int n = warp;
    int beg = rowptr[n], end = rowptr[n + 1];
    if (C == 32) {
        float acc = 0.f;
        for (int i = beg; i < end; i++) {
            int s = __ldg(&col[i]);
            acc += __ldg(&t[(size_t)s * 32 + lane]);
        }
        float v = fmaxf(dinv[n] * acc + __ldg(&bias[lane]), 0.f);
        out[(size_t)n * 32 + lane] = v;
    } else {
        float ax = 0.f, ay = 0.f;
        for (int i = beg; i < end; i++) {
            int s = __ldg(&col[i]);
            float2 v2 = *reinterpret_cast<const float2*>(&t[(size_t)s * 64 + 2 * lane]);
            ax += v2.x; ay += v2.y;
        }
        float dn = dinv[n];
        float2 b2 = __ldg(reinterpret_cast<const float2*>(&bias[2 * lane]));
        float vx = fmaxf(dn * ax + b2.x, 0.f);
        float vy = fmaxf(dn * ay + b2.y, 0.f);
        if (RESID) {
            float2 r2 = *reinterpret_cast<const float2*>(&resid[(size_t)n * 64 + 2 * lane]);
            vx += r2.x; vy += r2.y;
        }
        float2 r; r.x = vx; r.y = vy;
        *reinterpret_cast<float2*>(&out[(size_t)n * 64 + 2 * lane]) = r;
    }
}

// ---------------------------------------------------------------------------
// GAT per-node attention scores: a_s[n,h] = <g[n,h,:], att_src[h,:]>, same for a_d
// ---------------------------------------------------------------------------
__global__ void gat_scores_kernel(const float* __restrict__ g, const float* __restrict__ att_src,
                                  const float* __restrict__ att_dst, float* __restrict__ a_s,
                                  float* __restrict__ a_d, int n_nodes) {
    int i = blockIdx.x * blockDim.x + threadIdx.x;
    if (i >= n_nodes) return;
    const float* row = g + (size_t)i * 64;
#pragma unroll
    for (int h = 0; h < 4; h++) {
        float s = 0.f, d = 0.f;
#pragma unroll
        for (int c = 0; c < 16; c++) {
            float v = row[h * 16 + c];
            s += v * __ldg(&att_src[h * 16 + c]);
            d += v * __ldg(&att_dst[h * 16 + c]);
        }
        a_s[(size_t)i * 4 + h] = s;
        a_d[(size_t)i * 4 + h] = d;
    }
}

// ---------------------------------------------------------------------------
// GAT aggregation: warp-per-node, local segment-softmax (max / denom / weighted sum)
// out[n] = relu(sum_s alpha_{s->n} * g[s] + bias)
// ---------------------------------------------------------------------------
__global__ void gat_agg_kernel(const float* __restrict__ g, const float* __restrict__ a_s,
                               const float* __restrict__ a_d, const int* __restrict__ rowptr,
                               const int* __restrict__ col, const float* __restrict__ bias,
                               float* __restrict__ out, int n_nodes) {
    int warp = (blockIdx.x * blockDim.x + threadIdx.x) >> 5;
    int lane = threadIdx.x & 31;
    if (warp >= n_nodes) return;
    int n = warp;
    int beg = rowptr[n], end = rowptr[n + 1];
    float4 ad4 = *reinterpret_cast<const float4*>(&a_d[(size_t)n * 4]);

    // pass 1: per-head max over incoming edges (edge-per-lane)
    float m0 = -1e30f, m1 = -1e30f, m2 = -1e30f, m3 = -1e30f;
    for (int i = beg + lane; i < end; i += 32) {
        int s = __ldg(&col[i]);
        float4 as4 = __ldg(reinterpret_cast<const float4*>(&a_s[(size_t)s * 4]));
        m0 = fmaxf(m0, lrelu(as4.x + ad4.x));
        m1 = fmaxf(m1, lrelu(as4.y + ad4.y));
        m2 = fmaxf(m2, lrelu(as4.z + ad4.z));
        m3 = fmaxf(m3, lrelu(as4.w + ad4.w));
    }
#pragma unroll
    for (int o = 16; o; o >>= 1) {
        m0 = fmaxf(m0, __shfl_xor_sync(0xffffffffu, m0, o));
        m1 = fmaxf(m1, __shfl_xor_sync(0xffffffffu, m1, o));
        m2 = fmaxf(m2, __shfl_xor_sync(0xffffffffu, m2, o));
        m3 = fmaxf(m3, __shfl_xor_sync(0xffffffffu, m3, o));
    }

    // pass 2: per-head denominator
    float d0 = 0.f, d1 = 0.f, d2 = 0.f, d3 = 0.f;
    for (int i = beg + lane; i < end; i += 32) {
        int s = __ldg(&col[i]);
        float4 as4 = __ldg(reinterpret_cast<const float4*>(&a_s[(size_t)s * 4]));
        d0 += __expf(lrelu(as4.x + ad4.x) - m0);
        d1 += __expf(lrelu(as4.y + ad4.y) - m1);
        d2 += __expf(lrelu(as4.z + ad4.z) - m2);
        d3 += __expf(lrelu(as4.w + ad4.w) - m3);
    }
#pragma unroll
    for (int o = 16; o; o >>= 1) {
        d0 += __shfl_xor_sync(0xffffffffu, d0, o);
        d1 += __shfl_xor_sync(0xffffffffu, d1, o);
        d2 += __shfl_xor_sync(0xffffffffu, d2, o);
        d3 += __shfl_xor_sync(0xffffffffu, d3, o);
    }
    float r0 = 1.f / (d0 + 1e-16f), r1 = 1.f / (d1 + 1e-16f);
    float r2 = 1.f / (d2 + 1e-16f), r3 = 1.f / (d3 + 1e-16f);

    // pass 3: weighted aggregation (channel-pair-per-lane, sequential edges)
    int h = lane & 3;  // head this lane recomputes alpha for
    float mh  = (h == 0) ? m0 : (h == 1) ? m1 : (h == 2) ? m2 : m3;
    float adh = (h == 0) ? ad4.x : (h == 1) ? ad4.y : (h == 2) ? ad4.z : ad4.w;
    float rh  = (h == 0) ? r0 : (h == 1) ? r1 : (h == 2) ? r2 : r3;
    int hsel = lane >> 3;  // head of my channel pair; producer lane index == hsel
    float ax = 0.f, ay = 0.f;
    for (int i = beg; i < end; i++) {
        int s = __ldg(&col[i]);
        float asv = __ldg(&a_s[(size_t)s * 4 + h]);
        float al = __expf(lrelu(asv + adh) - mh) * rh;
        float alpha = __shfl_sync(0xffffffffu, al, hsel);
        float2 v2 = *reinterpret_cast<const float2*>(&g[(size_t)s * 64 + 2 * lane]);
        ax += alpha * v2.x;
        ay += alpha * v2.y;
    }
    float2 b2 = __ldg(reinterpret_cast<const float2*>(&bias[2 * lane]));
    float2 r;
    r.x = fmaxf(ax + b2.x, 0.f);
    r.y = fmaxf(ay + b2.y, 0.f);
    *reinterpret_cast<float2*>(&out[(size_t)n * 64 + 2 * lane]) = r;
}

// ---------------------------------------------------------------------------
// Final projection: out[n] = relu(<h[n], Wl> + bl)
// ---------------------------------------------------------------------------
__global__ void final_kernel(const float* __restrict__ h, const float* __restrict__ Wl,
                             const float* __restrict__ bl, float* __restrict__ out, int n_nodes) {
    int warp = (blockIdx.x * blockDim.x + threadIdx.x) >> 5;
    int lane = threadIdx.x & 31;
    if (warp >= n_nodes) return;
    float2 v = *reinterpret_cast<const float2*>(&h[(size_t)warp * 64 + 2 * lane]);
    float2 w = __ldg(reinterpret_cast<const float2*>(&Wl[2 * lane]));
    float p = v.x * w.x + v.y * w.y;
#pragma unroll
    for (int o = 16; o; o >>= 1) p += __shfl_xor_sync(0xffffffffu, p, o);
    if (lane == 0) out[warp] = fmaxf(p + __ldg(bl), 0.f);
}

// ---------------------------------------------------------------------------
// Launch
// ---------------------------------------------------------------------------
extern "C" void kernel_launch(void* const* d_in, const int* in_sizes, int n_in,
                              void* d_out, int out_size) {
    const float* x       = (const float*)d_in[0];
    const int*   ei      = (const int*)d_in[1];
    const float* W1      = (const float*)d_in[2];
    const float* b1      = (const float*)d_in[3];
    const float* W2      = (const float*)d_in[4];
    const float* b2      = (const float*)d_in[5];
    const float* W3      = (const float*)d_in[6];
    const float* b3      = (const float*)d_in[7];
    const float* Wg      = (const float*)d_in[8];
    const float* att_src = (const float*)d_in[9];
    const float* att_dst = (const float*)d_in[10];
    const float* bg      = (const float*)d_in[11];
    const float* Wl      = (const float*)d_in[12];
    const float* bl      = (const float*)d_in[13];
    float* out = (float*)d_out;

    const int* src = ei;
    const int* dst = ei + N_EDGES;

    float *pA, *pB, *pC, *pD, *pAS, *pAD, *pDinv;
    int *pDeg, *pRow, *pCur, *pCol;
    cudaGetSymbolAddress((void**)&pA, g_bufA);
    cudaGetSymbolAddress((void**)&pB, g_bufB);
    cudaGetSymbolAddress((void**)&pC, g_bufC);
    cudaGetSymbolAddress((void**)&pD, g_bufD);
    cudaGetSymbolAddress((void**)&pAS, g_as);
    cudaGetSymbolAddress((void**)&pAD, g_ad);
    cudaGetSymbolAddress((void**)&pDinv, g_dinv);
    cudaGetSymbolAddress((void**)&pDeg, g_deg);
    cudaGetSymbolAddress((void**)&pRow, g_rowptr);
    cudaGetSymbolAddress((void**)&pCur, g_cur);
    cudaGetSymbolAddress((void**)&pCol, g_col);

    const int TB = 256;
    const int gN  = (N_NODES + TB - 1) / TB;   // thread-per-node grids
    const int gE  = (N_EDGES + TB - 1) / TB;   // thread-per-edge grids
    const int gW  = (N_NODES + 7) / 8;         // warp-per-node grids (8 warps/block)

    // ---- build CSR (by dst), degrees, dinv ----
    init_deg_kernel<<<gN, TB>>>(pDeg, N_NODES);
    hist_kernel<<<gE, TB>>>(dst, pDeg, N_EDGES);
    scan_kernel<<<1, 1024>>>(pDeg, pRow, N_NODES);
    csr_init_kernel<<<gN, TB>>>(pRow, pDeg, pCur, pCol, pDinv, N_NODES);
    fill_kernel<<<gE, TB>>>(src, dst, pCur, pCol, N_EDGES);

    // ---- layer 1: GCN 128->32 ----
    gemm_kernel<128, 32, true><<<gW, TB>>>(x, W1, pDinv, pA, N_NODES);
    gcn_agg_kernel<32, false><<<gW, TB>>>(pA, pRow, pCol, pDinv, b1, nullptr, pB, N_NODES);

    // ---- layer 2: GCN 32->64 ----
    gemm_kernel<32, 64, true><<<gW, TB>>>(pB, W2, pDinv, pA, N_NODES);
    gcn_agg_kernel<64, false><<<gW, TB>>>(pA, pRow, pCol, pDinv, b2, nullptr, pB, N_NODES);

    // ---- layer 3: GAT (h2 -> h3) ----
    gemm_kernel<64, 64, false><<<gW, TB>>>(pB, Wg, pDinv, pA, N_NODES);
    gat_scores_kernel<<<gN, TB>>>(pA, att_src, att_dst, pAS, pAD, N_NODES);
    gat_agg_kernel<<<gW, TB>>>(pA, pAS, pAD, pRow, pCol, bg, pC, N_NODES);

    // ---- layer 4: GCN 64->64 residual: h4 = h3 + relu(agg + b3) ----
    gemm_kernel<64, 64, true><<<gW, TB>>>(pC, W3, pDinv, pA, N_NODES);
    gcn_agg_kernel<64, true><<<gW, TB>>>(pA, pRow, pCol, pDinv, b3, pC, pD, N_NODES);

    // ---- layer 5: GAT (h4 -> h5) ----
    gemm_kernel<64, 64, false><<<gW, TB>>>(pD, Wg, pDinv, pA, N_NODES);
    gat_scores_kernel<<<gN, TB>>>(pA, att_src, att_dst, pAS, pAD, N_NODES);
    gat_agg_kernel<<<gW, TB>>>(pA, pAS, pAD, pRow, pCol, bg, pB, N_NODES);

    // ---- final linear 64->1 ----
    final_kernel<<<gW, TB>>>(pB, Wl, bl, out, N_NODES);
}

// round 8
// speedup vs baseline: 1.5356x; 1.5356x over previous
#include <cuda_runtime.h>
#include <cstdint>

#define N_NODES 100000
#define N_EDGES 1600000
#define E_TOTAL (N_EDGES + N_NODES)   // 1,700,000
#define NB_SCAN ((N_NODES + 1023) / 1024)   // 98

// ---------------------------------------------------------------------------
// Scratch (device globals -- no allocation allowed)
// ---------------------------------------------------------------------------
__device__ int   g_deg[N_NODES];
__device__ int   g_rowptr[N_NODES + 1];
__device__ int   g_cur[N_NODES];
__device__ int   g_col[E_TOTAL];
__device__ int   g_bsum[128];
__device__ float g_dinv[N_NODES];
__device__ float g_bufA[(size_t)N_NODES * 64];
__device__ float g_bufB[(size_t)N_NODES * 64];
__device__ float g_bufC[(size_t)N_NODES * 64];
__device__ float g_bufD[(size_t)N_NODES * 64];
__device__ float g_as[(size_t)N_NODES * 4];
__device__ float g_ad[(size_t)N_NODES * 4];

__device__ __forceinline__ float lrelu(float x) { return x > 0.f ? x : 0.2f * x; }

union F2U { float2 f; unsigned long long u; };
__device__ __forceinline__ float2 ffma2(float2 a, float2 b, float2 c) {
    F2U ua, ub, uc; ua.f = a; ub.f = b; uc.f = c;
    asm("fma.rn.f32x2 %0, %1, %2, %0;" : "+l"(uc.u) : "l"(ua.u), "l"(ub.u));
    return uc.f;
}

// ---------------------------------------------------------------------------
// CSR build
// ---------------------------------------------------------------------------
__global__ void init_deg_kernel(int* deg, int n) {
    int i = blockIdx.x * blockDim.x + threadIdx.x;
    if (i < n) deg[i] = 1;  // self loop
}

__global__ void hist_kernel(const int* __restrict__ dst, int* __restrict__ deg, int e) {
    int i = blockIdx.x * blockDim.x + threadIdx.x;
    if (i < e) atomicAdd(&deg[dst[i]], 1);
}

// phase 1: per-block exclusive scan (1024 threads), partials + block totals
__global__ void scan1_kernel(const int* __restrict__ deg, int* __restrict__ part,
                             int* __restrict__ bsum, int n) {
    __shared__ int ws[32];
    int tid = threadIdx.x, lane = tid & 31, wid = tid >> 5;
    int i = blockIdx.x * 1024 + tid;
    int v = (i < n) ? deg[i] : 0;
    int x = v;
#pragma unroll
    for (int o = 1; o < 32; o <<= 1) {
        int t = __shfl_up_sync(0xffffffffu, x, o);
        if (lane >= o) x += t;
    }
    if (lane == 31) ws[wid] = x;
    __syncthreads();
    if (wid == 0) {
        int s = ws[lane];
        int y = s;
#pragma unroll
        for (int o = 1; o < 32; o <<= 1) {
            int t = __shfl_up_sync(0xffffffffu, y, o);
            if (lane >= o) y += t;
        }
        ws[lane] = y - s;                      // exclusive per-warp offset
        if (lane == 31) bsum[blockIdx.x] = y;  // block total
    }
    __syncthreads();
    if (i < n) part[i] = x - v + ws[wid];
}

// phase 2: exclusive scan of 98 block sums
__global__ void scan2_kernel(int* bsum, int nb) {
    __shared__ int ws[4];
    int tid = threadIdx.x, lane = tid & 31, wid = tid >> 5;
    int v = (tid < nb) ? bsum[tid] : 0;
    int x = v;
#pragma unroll
    for (int o = 1; o < 32; o <<= 1) {
        int t = __shfl_up_sync(0xffffffffu, x, o);
        if (lane >= o) x += t;
    }
    if (lane == 31) ws[wid] = x;
    __syncthreads();
    int off = 0;
    for (int w = 0; w < wid; w++) off += ws[w];
    if (tid < nb) bsum[tid] = x - v + off;
}

// phase 3 fused: finalize rowptr, self-loop slot, cur, dinv
__global__ void csr_init_kernel(int* __restrict__ rowptr, const int* __restrict__ bsum,
                                const int* __restrict__ deg, int* __restrict__ cur,
                                int* __restrict__ col, float* __restrict__ dinv, int n) {
    int i = blockIdx.x * blockDim.x + threadIdx.x;
    if (i >= n) return;
    int r = rowptr[i] + bsum[i >> 10];
    rowptr[i] = r;
    col[r] = i;          // self loop in slot 0
    cur[i] = r + 1;
    dinv[i] = rsqrtf((float)deg[i]);
    if (i == 0) rowptr[n] = E_TOTAL;
}

__global__ void fill_kernel(const int* __restrict__ src, const int* __restrict__ dst,
                            int* __restrict__ cur, int* __restrict__ col, int e) {
    int i = blockIdx.x * blockDim.x + threadIdx.x;
    if (i >= e) return;
    int p = atomicAdd(&cur[dst[i]], 1);
    col[p] = src[i];
}

// ---------------------------------------------------------------------------
// Layer-1 GEMM: t0 = (x @ W1) * dinv   (128 -> 32, warp-per-node, proven)
// ---------------------------------------------------------------------------
__global__ void gemm_l1_kernel(const float* __restrict__ in, const float* __restrict__ W,
                               const float* __restrict__ dinv, float* __restrict__ out,
                               int n_nodes) {
    __shared__ float Wsh[128 * 32];
    int tid = threadIdx.x;
    for (int i = tid; i < 128 * 32; i += blockDim.x) Wsh[i] = W[i];
    __syncthreads();
    int warp = tid >> 5, lane = tid & 31;
    int n = blockIdx.x * (blockDim.x >> 5) + warp;
    if (n >= n_nodes) return;
    const float4* xr = reinterpret_cast<const float4*>(in + (size_t)n * 128);
    float acc = 0.f;
#pragma unroll
    for (int k4 = 0; k4 < 32; k4++) {
        float4 x4 = __ldg(xr + k4);
        acc += x4.x * Wsh[(4 * k4 + 0) * 32 + lane];
        acc += x4.y * Wsh[(4 * k4 + 1) * 32 + lane];
        acc += x4.z * Wsh[(4 * k4 + 2) * 32 + lane];
        acc += x4.w * Wsh[(4 * k4 + 3) * 32 + lane];
    }
    acc *= dinv[n];
    out[(size_t)n * 32 + lane] = acc;
}

// ---------------------------------------------------------------------------
// 32-channel GCN aggregation (warp-per-node, 2 edges/iter via half-warps)
// MODE 0: out = relu(dinv*acc + b) * dinv      (layer 1)
// MODE 1: out = dinv*acc                       (layer 2 pre-GEMM aggregate)
// ---------------------------------------------------------------------------
template <int MODE>
__global__ void agg32_kernel(const float* __restrict__ t, const int* __restrict__ rowptr,
                             const int* __restrict__ col, const float* __restrict__ dinv,
                             const float* __restrict__ bias, float* __restrict__ out,
                             int n_nodes) {
    int warp = (blockIdx.x * blockDim.x + threadIdx.x) >> 5;
    if (warp >= n_nodes) return;
    int lane = threadIdx.x & 31;
    int half = lane >> 4, l16 = lane & 15;
    int beg = rowptr[warp], end = rowptr[warp + 1];
    float ax = 0.f, ay = 0.f;
#pragma unroll 4
    for (int i = beg + half; i < end; i += 2) {
        int s = __ldg(&col[i]);
        float2 v = *reinterpret_cast<const float2*>(&t[(size_t)s * 32 + 2 * l16]);
        ax += v.x; ay += v.y;
    }
    ax += __shfl_xor_sync(0xffffffffu, ax, 16);
    ay += __shfl_xor_sync(0xffffffffu, ay, 16);
    float dn = dinv[warp];
    if (MODE == 0) {
        float2 bv = __ldg(reinterpret_cast<const float2*>(&bias[2 * l16]));
        ax = fmaxf(dn * ax + bv.x, 0.f) * dn;
        ay = fmaxf(dn * ay + bv.y, 0.f) * dn;
    } else {
        ax *= dn; ay *= dn;
    }
    if (half == 0) {
        float2 r; r.x = ax; r.y = ay;
        *reinterpret_cast<float2*>(&out[(size_t)warp * 32 + 2 * l16]) = r;
    }
}

// ---------------------------------------------------------------------------
// 64-channel GCN pre-aggregate: z = dinv * sum t[s]   (layer 4)
// ---------------------------------------------------------------------------
__global__ void agg64_kernel(const float* __restrict__ t, const int* __restrict__ rowptr,
                             const int* __restrict__ col, const float* __restrict__ dinv,
                             float* __restrict__ out, int n_nodes) {
    int warp = (blockIdx.x * blockDim.x + threadIdx.x) >> 5;
    if (warp >= n_nodes) return;
    int lane = threadIdx.x & 31;
    int beg = rowptr[warp], end = rowptr[warp + 1];
    float ax = 0.f, ay = 0.f;
#pragma unroll 4
    for (int i = beg; i < end; i++) {
        int s = __ldg(&col[i]);
        float2 v = *reinterpret_cast<const float2*>(&t[(size_t)s * 64 + 2 * lane]);
        ax += v.x; ay += v.y;
    }
    float dn = dinv[warp];
    float2 r; r.x = ax * dn; r.y = ay * dn;
    *reinterpret_cast<float2*>(&out[(size_t)warp * 64 + 2 * lane]) = r;
}

// ---------------------------------------------------------------------------
// Fused transform: h = relu(z @ Wa + ba) [+ hres]; g = h @ Wg; GAT scores.
// 4 nodes/warp. Weights kept in NATURAL [k][64] layout; each lane owns the
// channel pair (2*lane, 2*lane+1) and loads it as an aligned, conflict-free
// float2 (LDS.64). The per-node input element x_k is lane-uniform and is
// broadcast into both halves of fma.rn.f32x2. Accumulator = channel pair.
// 3125 blocks x 256 threads = exactly 100000 nodes (no guards).
// ---------------------------------------------------------------------------
template <int CIN, bool RESID>
__global__ __launch_bounds__(256) void fused_transform_kernel(
    const float* __restrict__ z, const float* __restrict__ hres,
    const float* __restrict__ Wa, const float* __restrict__ ba,
    const float* __restrict__ Wg, const float* __restrict__ att_s,
    const float* __restrict__ att_d, float* __restrict__ gout,
    float* __restrict__ a_s, float* __restrict__ a_d) {
    __shared__ float Was[CIN * 64];
    __shared__ float Wgs[64 * 64];
    __shared__ float Hs[8][256];
    int tid = threadIdx.x;
    for (int i = tid; i < CIN * 64; i += 256) Was[i] = Wa[i];
    for (int i = tid; i < 64 * 64; i += 256) Wgs[i] = Wg[i];
    __syncthreads();
    int warp = tid >> 5, lane = tid & 31;
    int node0 = blockIdx.x * 32 + warp * 4;

    // gemm1: h = relu(z @ Wa + ba) [+ hres]
    float2 acc[4];
#pragma unroll
    for (int j = 0; j < 4; j++) acc[j] = make_float2(0.f, 0.f);
    for (int k = 0; k < CIN; k += 4) {
        float2 w0 = *reinterpret_cast<const float2*>(&Was[(k + 0) * 64 + 2 * lane]);
        float2 w1 = *reinterpret_cast<const float2*>(&Was[(k + 1) * 64 + 2 * lane]);
        float2 w2 = *reinterpret_cast<const float2*>(&Was[(k + 2) * 64 + 2 * lane]);
        float2 w3 = *reinterpret_cast<const float2*>(&Was[(k + 3) * 64 + 2 * lane]);
#pragma unroll
        for (int j = 0; j < 4; j++) {
            float4 xv = __ldg(reinterpret_cast<const float4*>(&z[(size_t)(node0 + j) * CIN + k]));
            acc[j] = ffma2(make_float2(xv.x, xv.x), w0, acc[j]);
            acc[j] = ffma2(make_float2(xv.y, xv.y), w1, acc[j]);
            acc[j] = ffma2(make_float2(xv.z, xv.z), w2, acc[j]);
            acc[j] = ffma2(make_float2(xv.w, xv.w), w3, acc[j]);
        }
    }
    float2 bv = __ldg(reinterpret_cast<const float2*>(&ba[2 * lane]));
#pragma unroll
    for (int j = 0; j < 4; j++) {
        float hx = fmaxf(acc[j].x + bv.x, 0.f);
        float hy = fmaxf(acc[j].y + bv.y, 0.f);
        if (RESID) {
            float2 rr = *reinterpret_cast<const float2*>(&hres[(size_t)(node0 + j) * 64 + 2 * lane]);
            hx += rr.x; hy += rr.y;
        }
        *reinterpret_cast<float2*>(&Hs[warp][j * 64 + 2 * lane]) = make_float2(hx, hy);
    }
    __syncwarp();

    // gemm2: g = h @ Wg   (Hs reads are lane-uniform broadcasts)
#pragma unroll
    for (int j = 0; j < 4; j++) acc[j] = make_float2(0.f, 0.f);
    for (int k = 0; k < 64; k += 4) {
        float2 w0 = *reinterpret_cast<const float2*>(&Wgs[(k + 0) * 64 + 2 * lane]);
        float2 w1 = *reinterpret_cast<const float2*>(&Wgs[(k + 1) * 64 + 2 * lane]);
        float2 w2 = *reinterpret_cast<const float2*>(&Wgs[(k + 2) * 64 + 2 * lane]);
        float2 w3 = *reinterpret_cast<const float2*>(&Wgs[(k + 3) * 64 + 2 * lane]);
#pragma unroll
        for (int j = 0; j < 4; j++) {
            float4 hv = *reinterpret_cast<const float4*>(&Hs[warp][j * 64 + k]);
            acc[j] = ffma2(make_float2(hv.x, hv.x), w0, acc[j]);
            acc[j] = ffma2(make_float2(hv.y, hv.y), w1, acc[j]);
            acc[j] = ffma2(make_float2(hv.z, hv.z), w2, acc[j]);
            acc[j] = ffma2(make_float2(hv.w, hv.w), w3, acc[j]);
        }
    }
    float ats0 = __ldg(&att_s[2 * lane]), ats1 = __ldg(&att_s[2 * lane + 1]);
    float atd0 = __ldg(&att_d[2 * lane]), atd1 = __ldg(&att_d[2 * lane + 1]);
#pragma unroll
    for (int j = 0; j < 4; j++) {
        int n = node0 + j;
        float gx = acc[j].x, gy = acc[j].y;
        *reinterpret_cast<float2*>(&gout[(size_t)n * 64 + 2 * lane]) = make_float2(gx, gy);
        float ps = gx * ats0 + gy * ats1;
        float pd = gx * atd0 + gy * atd1;
#pragma unroll
        for (int o = 1; o < 8; o <<= 1) {
            ps += __shfl_xor_sync(0xffffffffu, ps, o);
            pd += __shfl_xor_sync(0xffffffffu, pd, o);
        }
        if ((lane & 7) == 0) {
            a_s[(size_t)n * 4 + (lane >> 3)] = ps;
            a_d[(size_t)n * 4 + (lane >> 3)] = pd;
        }
    }
}

// ---------------------------------------------------------------------------
// GAT aggregation (warp-per-node, 3-pass segment softmax)
// FINAL=false: out1 = relu(agg+bias), out2 = out1*dinv
// FINAL=true : fout[n] = relu(<relu(agg+bias), Wl> + bl)
// ---------------------------------------------------------------------------
template <bool FINAL>
__global__ void gat_agg_kernel(const float* __restrict__ g, const float* __restrict__ a_s,
                               const float* __restrict__ a_d, const int* __restrict__ rowptr,
                               const int* __restrict__ col, const float* __restrict__ bias,
                               const float* __restrict__ dinv, float* __restrict__ out1,
                               float* __restrict__ out2, const float* __restrict__ Wl,
                               const float* __restrict__ bl, float* __restrict__ fout,
                               int n_nodes) {
    int warp = (blockIdx.x * blockDim.x + threadIdx.x) >> 5;
    int lane = threadIdx.x & 31;
    if (warp >= n_nodes) return;
    int n = warp;
    int beg = rowptr[n], end = rowptr[n + 1];
    float4 ad4 = *reinterpret_cast<const float4*>(&a_d[(size_t)n * 4]);

    // pass 1: per-head max (edge-per-lane)
    float m0 = -1e30f, m1 = -1e30f, m2 = -1e30f, m3 = -1e30f;
    for (int i = beg + lane; i < end; i += 32) {
        int s = __ldg(&col[i]);
        float4 as4 = __ldg(reinterpret_cast<const float4*>(&a_s[(size_t)s * 4]));
        m0 = fmaxf(m0, lrelu(as4.x + ad4.x));
        m1 = fmaxf(m1, lrelu(as4.y + ad4.y));
        m2 = fmaxf(m2, lrelu(as4.z + ad4.z));
        m3 = fmaxf(m3, lrelu(as4.w + ad4.w));
    }
#pragma unroll
    for (int o = 16; o; o >>= 1) {
        m0 = fmaxf(m0, __shfl_xor_sync(0xffffffffu, m0, o));
        m1 = fmaxf(m1, __shfl_xor_sync(0xffffffffu, m1, o));
        m2 = fmaxf(m2, __shfl_xor_sync(0xffffffffu, m2, o));
        m3 = fmaxf(m3, __shfl_xor_sync(0xffffffffu, m3, o));
    }

    // pass 2: per-head denominator
    float d0 = 0.f, d1 = 0.f, d2 = 0.f, d3 = 0.f;
    for (int i = beg + lane; i < end; i += 32) {
        int s = __ldg(&col[i]);
        float4 as4 = __ldg(reinterpret_cast<const float4*>(&a_s[(size_t)s * 4]));
        d0 += __expf(lrelu(as4.x + ad4.x) - m0);
        d1 += __expf(lrelu(as4.y + ad4.y) - m1);
        d2 += __expf(lrelu(as4.z + ad4.z) - m2);
        d3 += __expf(lrelu(as4.w + ad4.w) - m3);
    }
#pragma unroll
    for (int o = 16; o; o >>= 1) {
        d0 += __shfl_xor_sync(0xffffffffu, d0, o);
        d1 += __shfl_xor_sync(0xffffffffu, d1, o);
        d2 += __shfl_xor_sync(0xffffffffu, d2, o);
        d3 += __shfl_xor_sync(0xffffffffu, d3, o);
    }
    float r0 = 1.f / (d0 + 1e-16f), r1 = 1.f / (d1 + 1e-16f);
    float r2 = 1.f / (d2 + 1e-16f), r3 = 1.f / (d3 + 1e-16f);

    // pass 3: weighted gather (channel-pair-per-lane)
    int h = lane & 3;
    float mh  = (h == 0) ? m0 : (h == 1) ? m1 : (h == 2) ? m2 : m3;
    float adh = (h == 0) ? ad4.x : (h == 1) ? ad4.y : (h == 2) ? ad4.z : ad4.w;
    float rh  = (h == 0) ? r0 : (h == 1) ? r1 : (h == 2) ? r2 : r3;
    int hsel = lane >> 3;
    float ax = 0.f, ay = 0.f;
#pragma unroll 4
    for (int i = beg; i < end; i++) {
        int s = __ldg(&col[i]);
        float asv = __ldg(&a_s[(size_t)s * 4 + h]);
        float al = __expf(lrelu(asv + adh) - mh) * rh;
        float alpha = __shfl_sync(0xffffffffu, al, hsel);
        float2 v2 = *reinterpret_cast<const float2*>(&g[(size_t)s * 64 + 2 * lane]);
        ax += alpha * v2.x;
        ay += alpha * v2.y;
    }
    float2 b2 = __ldg(reinterpret_cast<const float2*>(&bias[2 * lane]));
    float hx = fmaxf(ax + b2.x, 0.f);
    float hy = fmaxf(ay + b2.y, 0.f);
    if (!FINAL) {
        *reinterpret_cast<float2*>(&out1[(size_t)n * 64 + 2 * lane]) = make_float2(hx, hy);
        float dn = dinv[n];
        *reinterpret_cast<float2*>(&out2[(size_t)n * 64 + 2 * lane]) = make_float2(hx * dn, hy * dn);
    } else {
        float2 w = __ldg(reinterpret_cast<const float2*>(&Wl[2 * lane]));
        float p = hx * w.x + hy * w.y;
#pragma unroll
        for (int o = 16; o; o >>= 1) p += __shfl_xor_sync(0xffffffffu, p, o);
        if (lane == 0) fout[n] = fmaxf(p + __ldg(bl), 0.f);
    }
}

// ---------------------------------------------------------------------------
// Launch
// ---------------------------------------------------------------------------
extern "C" void kernel_launch(void* const* d_in, const int* in_sizes, int n_in,
                              void* d_out, int out_size) {
    const float* x       = (const float*)d_in[0];
    const int*   ei      = (const int*)d_in[1];
    const float* W1      = (const float*)d_in[2];
    const float* b1      = (const float*)d_in[3];
    const float* W2      = (const float*)d_in[4];
    const float* b2      = (const float*)d_in[5];
    const float* W3      = (const float*)d_in[6];
    const float* b3      = (const float*)d_in[7];
    const float* Wg      = (const float*)d_in[8];
    const float* att_src = (const float*)d_in[9];
    const float* att_dst = (const float*)d_in[10];
    const float* bg      = (const float*)d_in[11];
    const float* Wl      = (const float*)d_in[12];
    const float* bl      = (const float*)d_in[13];
    float* out = (float*)d_out;

    const int* src = ei;
    const int* dst = ei + N_EDGES;

    float *pA, *pB, *pC, *pD, *pAS, *pAD, *pDinv;
    int *pDeg, *pRow, *pCur, *pCol, *pBsum;
    cudaGetSymbolAddress((void**)&pA, g_bufA);
    cudaGetSymbolAddress((void**)&pB, g_bufB);
    cudaGetSymbolAddress((void**)&pC, g_bufC);
    cudaGetSymbolAddress((void**)&pD, g_bufD);
    cudaGetSymbolAddress((void**)&pAS, g_as);
    cudaGetSymbolAddress((void**)&pAD, g_ad);
    cudaGetSymbolAddress((void**)&pDinv, g_dinv);
    cudaGetSymbolAddress((void**)&pDeg, g_deg);
    cudaGetSymbolAddress((void**)&pRow, g_rowptr);
    cudaGetSymbolAddress((void**)&pCur, g_cur);
    cudaGetSymbolAddress((void**)&pCol, g_col);
    cudaGetSymbolAddress((void**)&pBsum, g_bsum);

    const int TB = 256;
    const int gN = (N_NODES + TB - 1) / TB;
    const int gE = (N_EDGES + TB - 1) / TB;
    const int gW = (N_NODES + 7) / 8;     // warp-per-node, 8 warps/block
    const int gF = N_NODES / 32;          // fused transform: 32 nodes/block (3125)

    // ---- build CSR ----
    init_deg_kernel<<<gN, TB>>>(pDeg, N_NODES);
    hist_kernel<<<gE, TB>>>(dst, pDeg, N_EDGES);
    scan1_kernel<<<NB_SCAN, 1024>>>(pDeg, pRow, pBsum, N_NODES);
    scan2_kernel<<<1, 128>>>(pBsum, NB_SCAN);
    csr_init_kernel<<<gN, TB>>>(pRow, pBsum, pDeg, pCur, pCol, pDinv, N_NODES);
    fill_kernel<<<gE, TB>>>(src, dst, pCur, pCol, N_EDGES);

    // ---- layer 1: GCN 128->32 ----
    gemm_l1_kernel<<<gW, TB>>>(x, W1, pDinv, pA, N_NODES);                 // t0
    agg32_kernel<0><<<gW, TB>>>(pA, pRow, pCol, pDinv, b1, pB, N_NODES);   // t1 = h1*dinv

    // ---- layer 2 aggregate (32ch) then fused GEMMs ----
    agg32_kernel<1><<<gW, TB>>>(pB, pRow, pCol, pDinv, nullptr, pA, N_NODES);  // z2
    fused_transform_kernel<32, false><<<gF, TB>>>(pA, nullptr, W2, b2, Wg,
                                                  att_src, att_dst, pC, pAS, pAD);  // g3 + scores

    // ---- layer 3: GAT aggregate ----
    gat_agg_kernel<false><<<gW, TB>>>(pC, pAS, pAD, pRow, pCol, bg, pDinv,
                                      pD, pB, nullptr, nullptr, nullptr, N_NODES);  // h3, t3

    // ---- layer 4 aggregate (64ch) then fused GEMMs (with residual) ----
    agg64_kernel<<<gW, TB>>>(pB, pRow, pCol, pDinv, pA, N_NODES);          // z4
    fused_transform_kernel<64, true><<<gF, TB>>>(pA, pD, W3, b3, Wg,
                                                 att_src, att_dst, pC, pAS, pAD);   // g5 + scores

    // ---- layer 5: GAT aggregate + final projection ----
    gat_agg_kernel<true><<<gW, TB>>>(pC, pAS, pAD, pRow, pCol, bg, pDinv,
                                     nullptr, nullptr, Wl, bl, out, N_NODES);
}

// round 10
// speedup vs baseline: 1.7815x; 1.1602x over previous
#include <cuda_runtime.h>
#include <cstdint>

#define N_NODES 100000
#define N_EDGES 1600000
#define E_TOTAL (N_EDGES + N_NODES)   // 1,700,000
#define NB_SCAN ((N_NODES + 1023) / 1024)   // 98

// ---------------------------------------------------------------------------
// Scratch (device globals -- no allocation allowed)
// ---------------------------------------------------------------------------
__device__ int   g_deg[N_NODES];
__device__ int   g_rowptr[N_NODES + 1];
__device__ int   g_cur[N_NODES];
__device__ int   g_col[E_TOTAL];
__device__ int   g_bsum[128];
__device__ float g_dinv[N_NODES];
__device__ float g_bufA[(size_t)N_NODES * 64];
__device__ float g_bufB[(size_t)N_NODES * 64];
__device__ float g_bufC[(size_t)N_NODES * 64];
__device__ float g_bufD[(size_t)N_NODES * 64];
__device__ float g_as[(size_t)N_NODES * 4];
__device__ float g_ad[(size_t)N_NODES * 4];

__device__ __forceinline__ float lrelu(float x) { return x > 0.f ? x : 0.2f * x; }

union F2U { float2 f; unsigned long long u; };
__device__ __forceinline__ float2 ffma2(float2 a, float2 b, float2 c) {
    F2U ua, ub, uc; ua.f = a; ub.f = b; uc.f = c;
    asm("fma.rn.f32x2 %0, %1, %2, %0;" : "+l"(uc.u) : "l"(ua.u), "l"(ub.u));
    return uc.f;
}

// ---------------------------------------------------------------------------
// CSR build
// ---------------------------------------------------------------------------
__global__ void init_deg_kernel(int* deg, int n) {
    int i = blockIdx.x * blockDim.x + threadIdx.x;
    if (i < n) deg[i] = 1;  // self loop
}

__global__ void hist_kernel(const int* __restrict__ dst, int* __restrict__ deg, int e) {
    int i = blockIdx.x * blockDim.x + threadIdx.x;
    if (i < e) atomicAdd(&deg[dst[i]], 1);
}

// phase 1: per-block exclusive scan (1024 threads), partials + block totals
__global__ void scan1_kernel(const int* __restrict__ deg, int* __restrict__ part,
                             int* __restrict__ bsum, int n) {
    __shared__ int ws[32];
    int tid = threadIdx.x, lane = tid & 31, wid = tid >> 5;
    int i = blockIdx.x * 1024 + tid;
    int v = (i < n) ? deg[i] : 0;
    int x = v;
#pragma unroll
    for (int o = 1; o < 32; o <<= 1) {
        int t = __shfl_up_sync(0xffffffffu, x, o);
        if (lane >= o) x += t;
    }
    if (lane == 31) ws[wid] = x;
    __syncthreads();
    if (wid == 0) {
        int s = ws[lane];
        int y = s;
#pragma unroll
        for (int o = 1; o < 32; o <<= 1) {
            int t = __shfl_up_sync(0xffffffffu, y, o);
            if (lane >= o) y += t;
        }
        ws[lane] = y - s;                      // exclusive per-warp offset
        if (lane == 31) bsum[blockIdx.x] = y;  // block total
    }
    __syncthreads();
    if (i < n) part[i] = x - v + ws[wid];
}

// phase 2: exclusive scan of 98 block sums
__global__ void scan2_kernel(int* bsum, int nb) {
    __shared__ int ws[4];
    int tid = threadIdx.x, lane = tid & 31, wid = tid >> 5;
    int v = (tid < nb) ? bsum[tid] : 0;
    int x = v;
#pragma unroll
    for (int o = 1; o < 32; o <<= 1) {
        int t = __shfl_up_sync(0xffffffffu, x, o);
        if (lane >= o) x += t;
    }
    if (lane == 31) ws[wid] = x;
    __syncthreads();
    int off = 0;
    for (int w = 0; w < wid; w++) off += ws[w];
    if (tid < nb) bsum[tid] = x - v + off;
}

// phase 3 fused: finalize rowptr, self-loop slot, cur, dinv
__global__ void csr_init_kernel(int* __restrict__ rowptr, const int* __restrict__ bsum,
                                const int* __restrict__ deg, int* __restrict__ cur,
                                int* __restrict__ col, float* __restrict__ dinv, int n) {
    int i = blockIdx.x * blockDim.x + threadIdx.x;
    if (i >= n) return;
    int r = rowptr[i] + bsum[i >> 10];
    rowptr[i] = r;
    col[r] = i;          // self loop in slot 0
    cur[i] = r + 1;
    dinv[i] = rsqrtf((float)deg[i]);
    if (i == 0) rowptr[n] = E_TOTAL;
}

__global__ void fill_kernel(const int* __restrict__ src, const int* __restrict__ dst,
                            int* __restrict__ cur, int* __restrict__ col, int e) {
    int i = blockIdx.x * blockDim.x + threadIdx.x;
    if (i >= e) return;
    int p = atomicAdd(&cur[dst[i]], 1);
    col[p] = src[i];
}

// ---------------------------------------------------------------------------
// Layer-1 GEMM: t0 = (x @ W1) * dinv   (128 -> 32, warp-per-node, proven)
// ---------------------------------------------------------------------------
__global__ void gemm_l1_kernel(const float* __restrict__ in, const float* __restrict__ W,
                               const float* __restrict__ dinv, float* __restrict__ out,
                               int n_nodes) {
    __shared__ float Wsh[128 * 32];
    int tid = threadIdx.x;
    for (int i = tid; i < 128 * 32; i += blockDim.x) Wsh[i] = W[i];
    __syncthreads();
    int warp = tid >> 5, lane = tid & 31;
    int n = blockIdx.x * (blockDim.x >> 5) + warp;
    if (n >= n_nodes) return;
    const float4* xr = reinterpret_cast<const float4*>(in + (size_t)n * 128);
    float acc = 0.f;
#pragma unroll
    for (int k4 = 0; k4 < 32; k4++) {
        float4 x4 = __ldg(xr + k4);
        acc += x4.x * Wsh[(4 * k4 + 0) * 32 + lane];
        acc += x4.y * Wsh[(4 * k4 + 1) * 32 + lane];
        acc += x4.z * Wsh[(4 * k4 + 2) * 32 + lane];
        acc += x4.w * Wsh[(4 * k4 + 3) * 32 + lane];
    }
    acc *= dinv[n];
    out[(size_t)n * 32 + lane] = acc;
}

// ---------------------------------------------------------------------------
// 32-channel GCN aggregation (warp-per-node, 2 edges/iter via half-warps)
// MODE 0: out = relu(dinv*acc + b) * dinv      (layer 1)
// MODE 1: out = dinv*acc                       (layer 2 pre-GEMM aggregate)
// ---------------------------------------------------------------------------
template <int MODE>
__global__ void agg32_kernel(const float* __restrict__ t, const int* __restrict__ rowptr,
                             const int* __restrict__ col, const float* __restrict__ dinv,
                             const float* __restrict__ bias, float* __restrict__ out,
                             int n_nodes) {
    int warp = (blockIdx.x * blockDim.x + threadIdx.x) >> 5;
    if (warp >= n_nodes) return;
    int lane = threadIdx.x & 31;
    int half = lane >> 4, l16 = lane & 15;
    int beg = rowptr[warp], end = rowptr[warp + 1];
    float ax = 0.f, ay = 0.f;
#pragma unroll 4
    for (int i = beg + half; i < end; i += 2) {
        int s = __ldg(&col[i]);
        float2 v = *reinterpret_cast<const float2*>(&t[(size_t)s * 32 + 2 * l16]);
        ax += v.x; ay += v.y;
    }
    ax += __shfl_xor_sync(0xffffffffu, ax, 16);
    ay += __shfl_xor_sync(0xffffffffu, ay, 16);
    float dn = dinv[warp];
    if (MODE == 0) {
        float2 bv = __ldg(reinterpret_cast<const float2*>(&bias[2 * l16]));
        ax = fmaxf(dn * ax + bv.x, 0.f) * dn;
        ay = fmaxf(dn * ay + bv.y, 0.f) * dn;
    } else {
        ax *= dn; ay *= dn;
    }
    if (half == 0) {
        float2 r; r.x = ax; r.y = ay;
        *reinterpret_cast<float2*>(&out[(size_t)warp * 32 + 2 * l16]) = r;
    }
}

// ---------------------------------------------------------------------------
// 64-channel GCN pre-aggregate: z = dinv * sum t[s]   (layer 4)
// ---------------------------------------------------------------------------
__global__ void agg64_kernel(const float* __restrict__ t, const int* __restrict__ rowptr,
                             const int* __restrict__ col, const float* __restrict__ dinv,
                             float* __restrict__ out, int n_nodes) {
    int warp = (blockIdx.x * blockDim.x + threadIdx.x) >> 5;
    if (warp >= n_nodes) return;
    int lane = threadIdx.x & 31;
    int beg = rowptr[warp], end = rowptr[warp + 1];
    float ax = 0.f, ay = 0.f;
#pragma unroll 4
    for (int i = beg; i < end; i++) {
        int s = __ldg(&col[i]);
        float2 v = *reinterpret_cast<const float2*>(&t[(size_t)s * 64 + 2 * lane]);
        ax += v.x; ay += v.y;
    }
    float dn = dinv[warp];
    float2 r; r.x = ax * dn; r.y = ay * dn;
    *reinterpret_cast<float2*>(&out[(size_t)warp * 64 + 2 * lane]) = r;
}

// ---------------------------------------------------------------------------
// Fused transform: h = relu(z @ Wa + ba) [+ hres]; g = h @ Wg; GAT scores.
// 4 nodes/warp, natural [k][64] W layout, lane channel-pair float2, FFMA2.
// ---------------------------------------------------------------------------
template <int CIN, bool RESID>
__global__ __launch_bounds__(256) void fused_transform_kernel(
    const float* __restrict__ z, const float* __restrict__ hres,
    const float* __restrict__ Wa, const float* __restrict__ ba,
    const float* __restrict__ Wg, const float* __restrict__ att_s,
    const float* __restrict__ att_d, float* __restrict__ gout,
    float* __restrict__ a_s, float* __restrict__ a_d) {
    __shared__ float Was[CIN * 64];
    __shared__ float Wgs[64 * 64];
    __shared__ float Hs[8][256];
    int tid = threadIdx.x;
    for (int i = tid; i < CIN * 64; i += 256) Was[i] = Wa[i];
    for (int i = tid; i < 64 * 64; i += 256) Wgs[i] = Wg[i];
    __syncthreads();
    int warp = tid >> 5, lane = tid & 31;
    int node0 = blockIdx.x * 32 + warp * 4;

    // gemm1: h = relu(z @ Wa + ba) [+ hres]
    float2 acc[4];
#pragma unroll
    for (int j = 0; j < 4; j++) acc[j] = make_float2(0.f, 0.f);
    for (int k = 0; k < CIN; k += 4) {
        float2 w0 = *reinterpret_cast<const float2*>(&Was[(k + 0) * 64 + 2 * lane]);
        float2 w1 = *reinterpret_cast<const float2*>(&Was[(k + 1) * 64 + 2 * lane]);
        float2 w2 = *reinterpret_cast<const float2*>(&Was[(k + 2) * 64 + 2 * lane]);
        float2 w3 = *reinterpret_cast<const float2*>(&Was[(k + 3) * 64 + 2 * lane]);
#pragma unroll
        for (int j = 0; j < 4; j++) {
            float4 xv = __ldg(reinterpret_cast<const float4*>(&z[(size_t)(node0 + j) * CIN + k]));
            acc[j] = ffma2(make_float2(xv.x, xv.x), w0, acc[j]);
            acc[j] = ffma2(make_float2(xv.y, xv.y), w1, acc[j]);
            acc[j] = ffma2(make_float2(xv.z, xv.z), w2, acc[j]);
            acc[j] = ffma2(make_float2(xv.w, xv.w), w3, acc[j]);
        }
    }
    float2 bv = __ldg(reinterpret_cast<const float2*>(&ba[2 * lane]));
#pragma unroll
    for (int j = 0; j < 4; j++) {
        float hx = fmaxf(acc[j].x + bv.x, 0.f);
        float hy = fmaxf(acc[j].y + bv.y, 0.f);
        if (RESID) {
            float2 rr = *reinterpret_cast<const float2*>(&hres[(size_t)(node0 + j) * 64 + 2 * lane]);
            hx += rr.x; hy += rr.y;
        }
        *reinterpret_cast<float2*>(&Hs[warp][j * 64 + 2 * lane]) = make_float2(hx, hy);
    }
    __syncwarp();

    // gemm2: g = h @ Wg   (Hs reads are lane-uniform broadcasts)
#pragma unroll
    for (int j = 0; j < 4; j++) acc[j] = make_float2(0.f, 0.f);
    for (int k = 0; k < 64; k += 4) {
        float2 w0 = *reinterpret_cast<const float2*>(&Wgs[(k + 0) * 64 + 2 * lane]);
        float2 w1 = *reinterpret_cast<const float2*>(&Wgs[(k + 1) * 64 + 2 * lane]);
        float2 w2 = *reinterpret_cast<const float2*>(&Wgs[(k + 2) * 64 + 2 * lane]);
        float2 w3 = *reinterpret_cast<const float2*>(&Wgs[(k + 3) * 64 + 2 * lane]);
#pragma unroll
        for (int j = 0; j < 4; j++) {
            float4 hv = *reinterpret_cast<const float4*>(&Hs[warp][j * 64 + k]);
            acc[j] = ffma2(make_float2(hv.x, hv.x), w0, acc[j]);
            acc[j] = ffma2(make_float2(hv.y, hv.y), w1, acc[j]);
            acc[j] = ffma2(make_float2(hv.z, hv.z), w2, acc[j]);
            acc[j] = ffma2(make_float2(hv.w, hv.w), w3, acc[j]);
        }
    }
    float ats0 = __ldg(&att_s[2 * lane]), ats1 = __ldg(&att_s[2 * lane + 1]);
    float atd0 = __ldg(&att_d[2 * lane]), atd1 = __ldg(&att_d[2 * lane + 1]);
#pragma unroll
    for (int j = 0; j < 4; j++) {
        int n = node0 + j;
        float gx = acc[j].x, gy = acc[j].y;
        *reinterpret_cast<float2*>(&gout[(size_t)n * 64 + 2 * lane]) = make_float2(gx, gy);
        float ps = gx * ats0 + gy * ats1;
        float pd = gx * atd0 + gy * atd1;
#pragma unroll
        for (int o = 1; o < 8; o <<= 1) {
            ps += __shfl_xor_sync(0xffffffffu, ps, o);
            pd += __shfl_xor_sync(0xffffffffu, pd, o);
        }
        if ((lane & 7) == 0) {
            a_s[(size_t)n * 4 + (lane >> 3)] = ps;
            a_d[(size_t)n * 4 + (lane >> 3)] = pd;
        }
    }
}

// ---------------------------------------------------------------------------
// GAT aggregation (warp-per-node) with SMEM edge cache:
//   pass 1: gather a_s once, cache col + lrelu(e) per head in SMEM, track max
//   pass 2: ex = exp(e - m) from SMEM, store back, accumulate denom
//   pass 3: alpha = ex * 1/denom  (broadcast LDS; no exp, no shfl, no a_s)
// Fallback to the 3-pass global path for degree > CAP (correctness guard).
// FINAL=false: out1 = relu(agg+bias), out2 = out1*dinv
// FINAL=true : fout[n] = relu(<relu(agg+bias), Wl> + bl)
// ---------------------------------------------------------------------------
#define GAT_CAP 128

template <bool FINAL>
__global__ __launch_bounds__(256) void gat_agg_kernel(
    const float* __restrict__ g, const float* __restrict__ a_s,
    const float* __restrict__ a_d, const int* __restrict__ rowptr,
    const int* __restrict__ col, const float* __restrict__ bias,
    const float* __restrict__ dinv, float* __restrict__ out1,
    float* __restrict__ out2, const float* __restrict__ Wl,
    const float* __restrict__ bl, float* __restrict__ fout, int n_nodes) {
    __shared__ float ex_sh[8][GAT_CAP * 4];   // 16 KB
    __shared__ int   col_sh[8][GAT_CAP];      //  4 KB
    int gwarp = (blockIdx.x * blockDim.x + threadIdx.x) >> 5;
    if (gwarp >= n_nodes) return;
    int warp = threadIdx.x >> 5, lane = threadIdx.x & 31;
    int n = gwarp;
    int beg = rowptr[n], end = rowptr[n + 1];
    int deg = end - beg;
    float4 ad4 = *reinterpret_cast<const float4*>(&a_d[(size_t)n * 4]);

    float ax = 0.f, ay = 0.f;

    if (deg <= GAT_CAP) {
        // pass 1: gather + cache + max
        float m0 = -1e30f, m1 = -1e30f, m2 = -1e30f, m3 = -1e30f;
        for (int i = lane; i < deg; i += 32) {
            int s = __ldg(&col[beg + i]);
            col_sh[warp][i] = s;
            float4 as4 = __ldg(reinterpret_cast<const float4*>(&a_s[(size_t)s * 4]));
            float e0 = lrelu(as4.x + ad4.x);
            float e1 = lrelu(as4.y + ad4.y);
            float e2 = lrelu(as4.z + ad4.z);
            float e3 = lrelu(as4.w + ad4.w);
            *reinterpret_cast<float4*>(&ex_sh[warp][i * 4]) = make_float4(e0, e1, e2, e3);
            m0 = fmaxf(m0, e0); m1 = fmaxf(m1, e1);
            m2 = fmaxf(m2, e2); m3 = fmaxf(m3, e3);
        }
#pragma unroll
        for (int o = 16; o; o >>= 1) {
            m0 = fmaxf(m0, __shfl_xor_sync(0xffffffffu, m0, o));
            m1 = fmaxf(m1, __shfl_xor_sync(0xffffffffu, m1, o));
            m2 = fmaxf(m2, __shfl_xor_sync(0xffffffffu, m2, o));
            m3 = fmaxf(m3, __shfl_xor_sync(0xffffffffu, m3, o));
        }
        // pass 2: exp from SMEM, store back, denom
        float d0 = 0.f, d1 = 0.f, d2 = 0.f, d3 = 0.f;
        for (int i = lane; i < deg; i += 32) {
            float4 e = *reinterpret_cast<const float4*>(&ex_sh[warp][i * 4]);
            float x0 = __expf(e.x - m0), x1 = __expf(e.y - m1);
            float x2 = __expf(e.z - m2), x3 = __expf(e.w - m3);
            *reinterpret_cast<float4*>(&ex_sh[warp][i * 4]) = make_float4(x0, x1, x2, x3);
            d0 += x0; d1 += x1; d2 += x2; d3 += x3;
        }
#pragma unroll
        for (int o = 16; o; o >>= 1) {
            d0 += __shfl_xor_sync(0xffffffffu, d0, o);
            d1 += __shfl_xor_sync(0xffffffffu, d1, o);
            d2 += __shfl_xor_sync(0xffffffffu, d2, o);
            d3 += __shfl_xor_sync(0xffffffffu, d3, o);
        }
        int h = lane >> 3;   // head of this lane's channel pair
        float rh = 1.f / (((h == 0) ? d0 : (h == 1) ? d1 : (h == 2) ? d2 : d3) + 1e-16f);
        __syncwarp();
        // pass 3: weighted gather, alpha straight from SMEM
#pragma unroll 4
        for (int i = 0; i < deg; i++) {
            int s = col_sh[warp][i];
            float al = ex_sh[warp][i * 4 + h] * rh;
            float2 v2 = *reinterpret_cast<const float2*>(&g[(size_t)s * 64 + 2 * lane]);
            ax += al * v2.x;
            ay += al * v2.y;
        }
    } else {
        // fallback: 3-pass global path (rare)
        float m0 = -1e30f, m1 = -1e30f, m2 = -1e30f, m3 = -1e30f;
        for (int i = beg + lane; i < end; i += 32) {
            int s = __ldg(&col[i]);
            float4 as4 = __ldg(reinterpret_cast<const float4*>(&a_s[(size_t)s * 4]));
            m0 = fmaxf(m0, lrelu(as4.x + ad4.x));
            m1 = fmaxf(m1, lrelu(as4.y + ad4.y));
            m2 = fmaxf(m2, lrelu(as4.z + ad4.z));
            m3 = fmaxf(m3, lrelu(as4.w + ad4.w));
        }
#pragma unroll
        for (int o = 16; o; o >>= 1) {
            m0 = fmaxf(m0, __shfl_xor_sync(0xffffffffu, m0, o));
            m1 = fmaxf(m1, __shfl_xor_sync(0xffffffffu, m1, o));
            m2 = fmaxf(m2, __shfl_xor_sync(0xffffffffu, m2, o));
            m3 = fmaxf(m3, __shfl_xor_sync(0xffffffffu, m3, o));
        }
        float d0 = 0.f, d1 = 0.f, d2 = 0.f, d3 = 0.f;
        for (int i = beg + lane; i < end; i += 32) {
            int s = __ldg(&col[i]);
            float4 as4 = __ldg(reinterpret_cast<const float4*>(&a_s[(size_t)s * 4]));
            d0 += __expf(lrelu(as4.x + ad4.x) - m0);
            d1 += __expf(lrelu(as4.y + ad4.y) - m1);
            d2 += __expf(lrelu(as4.z + ad4.z) - m2);
            d3 += __expf(lrelu(as4.w + ad4.w) - m3);
        }
#pragma unroll
        for (int o = 16; o; o >>= 1) {
            d0 += __shfl_xor_sync(0xffffffffu, d0, o);
            d1 += __shfl_xor_sync(0xffffffffu, d1, o);
            d2 += __shfl_xor_sync(0xffffffffu, d2, o);
            d3 += __shfl_xor_sync(0xffffffffu, d3, o);
        }
        float r0 = 1.f / (d0 + 1e-16f), r1 = 1.f / (d1 + 1e-16f);
        float r2 = 1.f / (d2 + 1e-16f), r3 = 1.f / (d3 + 1e-16f);
        int h = lane & 3;
        float mh  = (h == 0) ? m0 : (h == 1) ? m1 : (h == 2) ? m2 : m3;
        float adh = (h == 0) ? ad4.x : (h == 1) ? ad4.y : (h == 2) ? ad4.z : ad4.w;
        float rh  = (h == 0) ? r0 : (h == 1) ? r1 : (h == 2) ? r2 : r3;
        int hsel = lane >> 3;
        for (int i = beg; i < end; i++) {
            int s = __ldg(&col[i]);
            float asv = __ldg(&a_s[(size_t)s * 4 + h]);
            float al = __expf(lrelu(asv + adh) - mh) * rh;
            float alpha = __shfl_sync(0xffffffffu, al, hsel);
            float2 v2 = *reinterpret_cast<const float2*>(&g[(size_t)s * 64 + 2 * lane]);
            ax += alpha * v2.x;
            ay += alpha * v2.y;
        }
    }

    float2 b2 = __ldg(reinterpret_cast<const float2*>(&bias[2 * lane]));
    float hx = fmaxf(ax + b2.x, 0.f);
    float hy = fmaxf(ay + b2.y, 0.f);
    if (!FINAL) {
        *reinterpret_cast<float2*>(&out1[(size_t)n * 64 + 2 * lane]) = make_float2(hx, hy);
        float dn = dinv[n];
        *reinterpret_cast<float2*>(&out2[(size_t)n * 64 + 2 * lane]) = make_float2(hx * dn, hy * dn);
    } else {
        float2 w = __ldg(reinterpret_cast<const float2*>(&Wl[2 * lane]));
        float p = hx * w.x + hy * w.y;
#pragma unroll
        for (int o = 16; o; o >>= 1) p += __shfl_xor_sync(0xffffffffu, p, o);
        if (lane == 0) fout[n] = fmaxf(p + __ldg(bl), 0.f);
    }
}

// ---------------------------------------------------------------------------
// Launch
// ---------------------------------------------------------------------------
extern "C" void kernel_launch(void* const* d_in, const int* in_sizes, int n_in,
                              void* d_out, int out_size) {
    const float* x       = (const float*)d_in[0];
    const int*   ei      = (const int*)d_in[1];
    const float* W1      = (const float*)d_in[2];
    const float* b1      = (const float*)d_in[3];
    const float* W2      = (const float*)d_in[4];
    const float* b2      = (const float*)d_in[5];
    const float* W3      = (const float*)d_in[6];
    const float* b3      = (const float*)d_in[7];
    const float* Wg      = (const float*)d_in[8];
    const float* att_src = (const float*)d_in[9];
    const float* att_dst = (const float*)d_in[10];
    const float* bg      = (const float*)d_in[11];
    const float* Wl      = (const float*)d_in[12];
    const float* bl      = (const float*)d_in[13];
    float* out = (float*)d_out;

    const int* src = ei;
    const int* dst = ei + N_EDGES;

    float *pA, *pB, *pC, *pD, *pAS, *pAD, *pDinv;
    int *pDeg, *pRow, *pCur, *pCol, *pBsum;
    cudaGetSymbolAddress((void**)&pA, g_bufA);
    cudaGetSymbolAddress((void**)&pB, g_bufB);
    cudaGetSymbolAddress((void**)&pC, g_bufC);
    cudaGetSymbolAddress((void**)&pD, g_bufD);
    cudaGetSymbolAddress((void**)&pAS, g_as);
    cudaGetSymbolAddress((void**)&pAD, g_ad);
    cudaGetSymbolAddress((void**)&pDinv, g_dinv);
    cudaGetSymbolAddress((void**)&pDeg, g_deg);
    cudaGetSymbolAddress((void**)&pRow, g_rowptr);
    cudaGetSymbolAddress((void**)&pCur, g_cur);
    cudaGetSymbolAddress((void**)&pCol, g_col);
    cudaGetSymbolAddress((void**)&pBsum, g_bsum);

    const int TB = 256;
    const int gN = (N_NODES + TB - 1) / TB;
    const int gE = (N_EDGES + TB - 1) / TB;
    const int gW = (N_NODES + 7) / 8;     // warp-per-node, 8 warps/block
    const int gF = N_NODES / 32;          // fused transform: 32 nodes/block (3125)

    // ---- build CSR ----
    init_deg_kernel<<<gN, TB>>>(pDeg, N_NODES);
    hist_kernel<<<gE, TB>>>(dst, pDeg, N_EDGES);
    scan1_kernel<<<NB_SCAN, 1024>>>(pDeg, pRow, pBsum, N_NODES);
    scan2_kernel<<<1, 128>>>(pBsum, NB_SCAN);
    csr_init_kernel<<<gN, TB>>>(pRow, pBsum, pDeg, pCur, pCol, pDinv, N_NODES);
    fill_kernel<<<gE, TB>>>(src, dst, pCur, pCol, N_EDGES);

    // ---- layer 1: GCN 128->32 ----
    gemm_l1_kernel<<<gW, TB>>>(x, W1, pDinv, pA, N_NODES);                 // t0
    agg32_kernel<0><<<gW, TB>>>(pA, pRow, pCol, pDinv, b1, pB, N_NODES);   // t1 = h1*dinv

    // ---- layer 2 aggregate (32ch) then fused GEMMs ----
    agg32_kernel<1><<<gW, TB>>>(pB, pRow, pCol, pDinv, nullptr, pA, N_NODES);  // z2
    fused_transform_kernel<32, false><<<gF, TB>>>(pA, nullptr, W2, b2, Wg,
                                                  att_src, att_dst, pC, pAS, pAD);  // g3 + scores

    // ---- layer 3: GAT aggregate ----
    gat_agg_kernel<false><<<gW, TB>>>(pC, pAS, pAD, pRow, pCol, bg, pDinv,
                                      pD, pB, nullptr, nullptr, nullptr, N_NODES);  // h3, t3

    // ---- layer 4 aggregate (64ch) then fused GEMMs (with residual) ----
    agg64_kernel<<<gW, TB>>>(pB, pRow, pCol, pDinv, pA, N_NODES);          // z4
    fused_transform_kernel<64, true><<<gF, TB>>>(pA, pD, W3, b3, Wg,
                                                 att_src, att_dst, pC, pAS, pAD);   // g5 + scores

    // ---- layer 5: GAT aggregate + final projection ----
    gat_agg_kernel<true><<<gW, TB>>>(pC, pAS, pAD, pRow, pCol, bg, pDinv,
                                     nullptr, nullptr, Wl, bl, out, N_NODES);
}

// round 12
// speedup vs baseline: 1.8036x; 1.0124x over previous
#include <cuda_runtime.h>
#include <cstdint>

#define N_NODES 100000
#define N_EDGES 1600000
#define E_TOTAL (N_EDGES + N_NODES)   // 1,700,000
#define NB_SCAN ((N_NODES + 1023) / 1024)   // 98

// ---------------------------------------------------------------------------
// Scratch (device globals -- no allocation allowed)
// ---------------------------------------------------------------------------
__device__ int   g_deg[N_NODES];
__device__ int   g_rowptr[N_NODES + 1];
__device__ int   g_cur[N_NODES];
__device__ int   g_col[E_TOTAL];
__device__ int   g_bsum[128];
__device__ float g_dinv[N_NODES];
__device__ float g_bufA[(size_t)N_NODES * 64];
__device__ float g_bufB[(size_t)N_NODES * 64];
__device__ float g_bufC[(size_t)N_NODES * 64];
__device__ float g_bufD[(size_t)N_NODES * 64];
__device__ float g_as[(size_t)N_NODES * 4];
__device__ float g_ad[(size_t)N_NODES * 4];

__device__ __forceinline__ float lrelu(float x) { return x > 0.f ? x : 0.2f * x; }

union F2U { float2 f; unsigned long long u; };
__device__ __forceinline__ float2 ffma2(float2 a, float2 b, float2 c) {
    F2U ua, ub, uc; ua.f = a; ub.f = b; uc.f = c;
    asm("fma.rn.f32x2 %0, %1, %2, %0;" : "+l"(uc.u) : "l"(ua.u), "l"(ub.u));
    return uc.f;
}

// ---------------------------------------------------------------------------
// CSR build
// ---------------------------------------------------------------------------
__global__ void init_deg_kernel(int* deg, int n) {
    int i = blockIdx.x * blockDim.x + threadIdx.x;
    if (i < n) deg[i] = 1;  // self loop
}

__global__ void hist_kernel(const int* __restrict__ dst, int* __restrict__ deg, int e) {
    int i = blockIdx.x * blockDim.x + threadIdx.x;
    if (i < e) atomicAdd(&deg[dst[i]], 1);
}

// phase 1: per-block exclusive scan (1024 threads), partials + block totals
__global__ void scan1_kernel(const int* __restrict__ deg, int* __restrict__ part,
                             int* __restrict__ bsum, int n) {
    __shared__ int ws[32];
    int tid = threadIdx.x, lane = tid & 31, wid = tid >> 5;
    int i = blockIdx.x * 1024 + tid;
    int v = (i < n) ? deg[i] : 0;
    int x = v;
#pragma unroll
    for (int o = 1; o < 32; o <<= 1) {
        int t = __shfl_up_sync(0xffffffffu, x, o);
        if (lane >= o) x += t;
    }
    if (lane == 31) ws[wid] = x;
    __syncthreads();
    if (wid == 0) {
        int s = ws[lane];
        int y = s;
#pragma unroll
        for (int o = 1; o < 32; o <<= 1) {
            int t = __shfl_up_sync(0xffffffffu, y, o);
            if (lane >= o) y += t;
        }
        ws[lane] = y - s;                      // exclusive per-warp offset
        if (lane == 31) bsum[blockIdx.x] = y;  // block total
    }
    __syncthreads();
    if (i < n) part[i] = x - v + ws[wid];
}

// phase 2: exclusive scan of 98 block sums
__global__ void scan2_kernel(int* bsum, int nb) {
    __shared__ int ws[4];
    int tid = threadIdx.x, lane = tid & 31, wid = tid >> 5;
    int v = (tid < nb) ? bsum[tid] : 0;
    int x = v;
#pragma unroll
    for (int o = 1; o < 32; o <<= 1) {
        int t = __shfl_up_sync(0xffffffffu, x, o);
        if (lane >= o) x += t;
    }
    if (lane == 31) ws[wid] = x;
    __syncthreads();
    int off = 0;
    for (int w = 0; w < wid; w++) off += ws[w];
    if (tid < nb) bsum[tid] = x - v + off;
}

// phase 3 fused: finalize rowptr, self-loop slot, cur, dinv
__global__ void csr_init_kernel(int* __restrict__ rowptr, const int* __restrict__ bsum,
                                const int* __restrict__ deg, int* __restrict__ cur,
                                int* __restrict__ col, float* __restrict__ dinv, int n) {
    int i = blockIdx.x * blockDim.x + threadIdx.x;
    if (i >= n) return;
    int r = rowptr[i] + bsum[i >> 10];
    rowptr[i] = r;
    col[r] = i;          // self loop in slot 0
    cur[i] = r + 1;
    dinv[i] = rsqrtf((float)deg[i]);
    if (i == 0) rowptr[n] = E_TOTAL;
}

__global__ void fill_kernel(const int* __restrict__ src, const int* __restrict__ dst,
                            int* __restrict__ cur, int* __restrict__ col, int e) {
    int i = blockIdx.x * blockDim.x + threadIdx.x;
    if (i >= e) return;
    int p = atomicAdd(&cur[dst[i]], 1);
    col[p] = src[i];
}

// ---------------------------------------------------------------------------
// Layer-1 GEMM: t0 = (x @ W1) * dinv   (128 -> 32, warp-per-node, proven)
// ---------------------------------------------------------------------------
__global__ void gemm_l1_kernel(const float* __restrict__ in, const float* __restrict__ W,
                               const float* __restrict__ dinv, float* __restrict__ out,
                               int n_nodes) {
    __shared__ float Wsh[128 * 32];
    int tid = threadIdx.x;
    for (int i = tid; i < 128 * 32; i += blockDim.x) Wsh[i] = W[i];
    __syncthreads();
    int warp = tid >> 5, lane = tid & 31;
    int n = blockIdx.x * (blockDim.x >> 5) + warp;
    if (n >= n_nodes) return;
    const float4* xr = reinterpret_cast<const float4*>(in + (size_t)n * 128);
    float acc = 0.f;
#pragma unroll
    for (int k4 = 0; k4 < 32; k4++) {
        float4 x4 = __ldg(xr + k4);
        acc += x4.x * Wsh[(4 * k4 + 0) * 32 + lane];
        acc += x4.y * Wsh[(4 * k4 + 1) * 32 + lane];
        acc += x4.z * Wsh[(4 * k4 + 2) * 32 + lane];
        acc += x4.w * Wsh[(4 * k4 + 3) * 32 + lane];
    }
    acc *= dinv[n];
    out[(size_t)n * 32 + lane] = acc;
}

// ---------------------------------------------------------------------------
// 32-channel GCN aggregation: quarter-warp float4 (4 edges in flight/iter)
// MODE 0: out = relu(dinv*acc + b) * dinv      (layer 1)
// MODE 1: out = dinv*acc                       (layer 2 pre-GEMM aggregate)
// ---------------------------------------------------------------------------
template <int MODE>
__global__ void agg32_kernel(const float* __restrict__ t, const int* __restrict__ rowptr,
                             const int* __restrict__ col, const float* __restrict__ dinv,
                             const float* __restrict__ bias, float* __restrict__ out,
                             int n_nodes) {
    int warp = (blockIdx.x * blockDim.x + threadIdx.x) >> 5;
    if (warp >= n_nodes) return;
    int lane = threadIdx.x & 31;
    int q = lane >> 3, l8 = lane & 7;
    int beg = rowptr[warp], end = rowptr[warp + 1];
    float ax = 0.f, ay = 0.f, az = 0.f, aw = 0.f;
#pragma unroll 4
    for (int i = beg + q; i < end; i += 4) {
        int s = __ldg(&col[i]);
        float4 v = *reinterpret_cast<const float4*>(&t[(size_t)s * 32 + 4 * l8]);
        ax += v.x; ay += v.y; az += v.z; aw += v.w;
    }
#pragma unroll
    for (int o = 8; o <= 16; o <<= 1) {
        ax += __shfl_xor_sync(0xffffffffu, ax, o);
        ay += __shfl_xor_sync(0xffffffffu, ay, o);
        az += __shfl_xor_sync(0xffffffffu, az, o);
        aw += __shfl_xor_sync(0xffffffffu, aw, o);
    }
    float dn = dinv[warp];
    if (MODE == 0) {
        float4 bv = __ldg(reinterpret_cast<const float4*>(&bias[4 * l8]));
        ax = fmaxf(dn * ax + bv.x, 0.f) * dn;
        ay = fmaxf(dn * ay + bv.y, 0.f) * dn;
        az = fmaxf(dn * az + bv.z, 0.f) * dn;
        aw = fmaxf(dn * aw + bv.w, 0.f) * dn;
    } else {
        ax *= dn; ay *= dn; az *= dn; aw *= dn;
    }
    if (lane < 8) {
        *reinterpret_cast<float4*>(&out[(size_t)warp * 32 + 4 * l8]) =
            make_float4(ax, ay, az, aw);
    }
}

// ---------------------------------------------------------------------------
// 64-channel GCN pre-aggregate: half-warp float4 (2 edges in flight/iter)
// z = dinv * sum t[s]   (layer 4)
// ---------------------------------------------------------------------------
__global__ void agg64_kernel(const float* __restrict__ t, const int* __restrict__ rowptr,
                             const int* __restrict__ col, const float* __restrict__ dinv,
                             float* __restrict__ out, int n_nodes) {
    int warp = (blockIdx.x * blockDim.x + threadIdx.x) >> 5;
    if (warp >= n_nodes) return;
    int lane = threadIdx.x & 31;
    int h = lane >> 4, l16 = lane & 15;
    int beg = rowptr[warp], end = rowptr[warp + 1];
    float ax = 0.f, ay = 0.f, az = 0.f, aw = 0.f;
#pragma unroll 4
    for (int i = beg + h; i < end; i += 2) {
        int s = __ldg(&col[i]);
        float4 v = *reinterpret_cast<const float4*>(&t[(size_t)s * 64 + 4 * l16]);
        ax += v.x; ay += v.y; az += v.z; aw += v.w;
    }
    ax += __shfl_xor_sync(0xffffffffu, ax, 16);
    ay += __shfl_xor_sync(0xffffffffu, ay, 16);
    az += __shfl_xor_sync(0xffffffffu, az, 16);
    aw += __shfl_xor_sync(0xffffffffu, aw, 16);
    float dn = dinv[warp];
    if (lane < 16) {
        *reinterpret_cast<float4*>(&out[(size_t)warp * 64 + 4 * l16]) =
            make_float4(ax * dn, ay * dn, az * dn, aw * dn);
    }
}

// ---------------------------------------------------------------------------
// Fused transform: h = relu(z @ Wa + ba) [+ hres]; g = h @ Wg; GAT scores.
// 4 nodes/warp, natural [k][64] W layout, lane channel-pair float2, FFMA2.
// ---------------------------------------------------------------------------
template <int CIN, bool RESID>
__global__ __launch_bounds__(256) void fused_transform_kernel(
    const float* __restrict__ z, const float* __restrict__ hres,
    const float* __restrict__ Wa, const float* __restrict__ ba,
    const float* __restrict__ Wg, const float* __restrict__ att_s,
    const float* __restrict__ att_d, float* __restrict__ gout,
    float* __restrict__ a_s, float* __restrict__ a_d) {
    __shared__ float Was[CIN * 64];
    __shared__ float Wgs[64 * 64];
    __shared__ float Hs[8][256];
    int tid = threadIdx.x;
    for (int i = tid; i < CIN * 64; i += 256) Was[i] = Wa[i];
    for (int i = tid; i < 64 * 64; i += 256) Wgs[i] = Wg[i];
    __syncthreads();
    int warp = tid >> 5, lane = tid & 31;
    int node0 = blockIdx.x * 32 + warp * 4;

    // gemm1: h = relu(z @ Wa + ba) [+ hres]
    float2 acc[4];
#pragma unroll
    for (int j = 0; j < 4; j++) acc[j] = make_float2(0.f, 0.f);
    for (int k = 0; k < CIN; k += 4) {
        float2 w0 = *reinterpret_cast<const float2*>(&Was[(k + 0) * 64 + 2 * lane]);
        float2 w1 = *reinterpret_cast<const float2*>(&Was[(k + 1) * 64 + 2 * lane]);
        float2 w2 = *reinterpret_cast<const float2*>(&Was[(k + 2) * 64 + 2 * lane]);
        float2 w3 = *reinterpret_cast<const float2*>(&Was[(k + 3) * 64 + 2 * lane]);
#pragma unroll
        for (int j = 0; j < 4; j++) {
            float4 xv = __ldg(reinterpret_cast<const float4*>(&z[(size_t)(node0 + j) * CIN + k]));
            acc[j] = ffma2(make_float2(xv.x, xv.x), w0, acc[j]);
            acc[j] = ffma2(make_float2(xv.y, xv.y), w1, acc[j]);
            acc[j] = ffma2(make_float2(xv.z, xv.z), w2, acc[j]);
            acc[j] = ffma2(make_float2(xv.w, xv.w), w3, acc[j]);
        }
    }
    float2 bv = __ldg(reinterpret_cast<const float2*>(&ba[2 * lane]));
#pragma unroll
    for (int j = 0; j < 4; j++) {
        float hx = fmaxf(acc[j].x + bv.x, 0.f);
        float hy = fmaxf(acc[j].y + bv.y, 0.f);
        if (RESID) {
            float2 rr = *reinterpret_cast<const float2*>(&hres[(size_t)(node0 + j) * 64 + 2 * lane]);
            hx += rr.x; hy += rr.y;
        }
        *reinterpret_cast<float2*>(&Hs[warp][j * 64 + 2 * lane]) = make_float2(hx, hy);
    }
    __syncwarp();

    // gemm2: g = h @ Wg   (Hs reads are lane-uniform broadcasts)
#pragma unroll
    for (int j = 0; j < 4; j++) acc[j] = make_float2(0.f, 0.f);
    for (int k = 0; k < 64; k += 4) {
        float2 w0 = *reinterpret_cast<const float2*>(&Wgs[(k + 0) * 64 + 2 * lane]);
        float2 w1 = *reinterpret_cast<const float2*>(&Wgs[(k + 1) * 64 + 2 * lane]);
        float2 w2 = *reinterpret_cast<const float2*>(&Wgs[(k + 2) * 64 + 2 * lane]);
        float2 w3 = *reinterpret_cast<const float2*>(&Wgs[(k + 3) * 64 + 2 * lane]);
#pragma unroll
        for (int j = 0; j < 4; j++) {
            float4 hv = *reinterpret_cast<const float4*>(&Hs[warp][j * 64 + k]);
            acc[j] = ffma2(make_float2(hv.x, hv.x), w0, acc[j]);
            acc[j] = ffma2(make_float2(hv.y, hv.y), w1, acc[j]);
            acc[j] = ffma2(make_float2(hv.z, hv.z), w2, acc[j]);
            acc[j] = ffma2(make_float2(hv.w, hv.w), w3, acc[j]);
        }
    }
    float ats0 = __ldg(&att_s[2 * lane]), ats1 = __ldg(&att_s[2 * lane + 1]);
    float atd0 = __ldg(&att_d[2 * lane]), atd1 = __ldg(&att_d[2 * lane + 1]);
#pragma unroll
    for (int j = 0; j < 4; j++) {
        int n = node0 + j;
        float gx = acc[j].x, gy = acc[j].y;
        *reinterpret_cast<float2*>(&gout[(size_t)n * 64 + 2 * lane]) = make_float2(gx, gy);
        float ps = gx * ats0 + gy * ats1;
        float pd = gx * atd0 + gy * atd1;
#pragma unroll
        for (int o = 1; o < 8; o <<= 1) {
            ps += __shfl_xor_sync(0xffffffffu, ps, o);
            pd += __shfl_xor_sync(0xffffffffu, pd, o);
        }
        if ((lane & 7) == 0) {
            a_s[(size_t)n * 4 + (lane >> 3)] = ps;
            a_d[(size_t)n * 4 + (lane >> 3)] = pd;
        }
    }
}

// ---------------------------------------------------------------------------
// GAT aggregation (warp-per-node) with SMEM edge cache + half-warp float4
// pass 3 (2 edges in flight/iter).
// Fallback to the 3-pass global path for degree > CAP (correctness guard).
// FINAL=false: out1 = relu(agg+bias), out2 = out1*dinv
// FINAL=true : fout[n] = relu(<relu(agg+bias), Wl> + bl)
// ---------------------------------------------------------------------------
#define GAT_CAP 128

template <bool FINAL>
__global__ __launch_bounds__(256) void gat_agg_kernel(
    const float* __restrict__ g, const float* __restrict__ a_s,
    const float* __restrict__ a_d, const int* __restrict__ rowptr,
    const int* __restrict__ col, const float* __restrict__ bias,
    const float* __restrict__ dinv, float* __restrict__ out1,
    float* __restrict__ out2, const float* __restrict__ Wl,
    const float* __restrict__ bl, float* __restrict__ fout, int n_nodes) {
    __shared__ float ex_sh[8][GAT_CAP * 4];   // 16 KB
    __shared__ int   col_sh[8][GAT_CAP];      //  4 KB
    int gwarp = (blockIdx.x * blockDim.x + threadIdx.x) >> 5;
    if (gwarp >= n_nodes) return;
    int warp = threadIdx.x >> 5, lane = threadIdx.x & 31;
    int n = gwarp;
    int beg = rowptr[n], end = rowptr[n + 1];
    int deg = end - beg;
    float4 ad4 = *reinterpret_cast<const float4*>(&a_d[(size_t)n * 4]);

    if (deg <= GAT_CAP) {
        // pass 1: gather a_s once, cache col + lrelu(e), track per-head max
        float m0 = -1e30f, m1 = -1e30f, m2 = -1e30f, m3 = -1e30f;
        for (int i = lane; i < deg; i += 32) {
            int s = __ldg(&col[beg + i]);
            col_sh[warp][i] = s;
            float4 as4 = __ldg(reinterpret_cast<const float4*>(&a_s[(size_t)s * 4]));
            float e0 = lrelu(as4.x + ad4.x);
            float e1 = lrelu(as4.y + ad4.y);
            float e2 = lrelu(as4.z + ad4.z);
            float e3 = lrelu(as4.w + ad4.w);
            *reinterpret_cast<float4*>(&ex_sh[warp][i * 4]) = make_float4(e0, e1, e2, e3);
            m0 = fmaxf(m0, e0); m1 = fmaxf(m1, e1);
            m2 = fmaxf(m2, e2); m3 = fmaxf(m3, e3);
        }
#pragma unroll
        for (int o = 16; o; o >>= 1) {
            m0 = fmaxf(m0, __shfl_xor_sync(0xffffffffu, m0, o));
            m1 = fmaxf(m1, __shfl_xor_sync(0xffffffffu, m1, o));
            m2 = fmaxf(m2, __shfl_xor_sync(0xffffffffu, m2, o));
            m3 = fmaxf(m3, __shfl_xor_sync(0xffffffffu, m3, o));
        }
        // pass 2: exp from SMEM, store back, denom
        float d0 = 0.f, d1 = 0.f, d2 = 0.f, d3 = 0.f;
        for (int i = lane; i < deg; i += 32) {
            float4 e = *reinterpret_cast<const float4*>(&ex_sh[warp][i * 4]);
            float x0 = __expf(e.x - m0), x1 = __expf(e.y - m1);
            float x2 = __expf(e.z - m2), x3 = __expf(e.w - m3);
            *reinterpret_cast<float4*>(&ex_sh[warp][i * 4]) = make_float4(x0, x1, x2, x3);
            d0 += x0; d1 += x1; d2 += x2; d3 += x3;
        }
#pragma unroll
        for (int o = 16; o; o >>= 1) {
            d0 += __shfl_xor_sync(0xffffffffu, d0, o);
            d1 += __shfl_xor_sync(0xffffffffu, d1, o);
            d2 += __shfl_xor_sync(0xffffffffu, d2, o);
            d3 += __shfl_xor_sync(0xffffffffu, d3, o);
        }
        // half-warp float4 pass 3: lanes h*16..h*16+15 handle edges i = h mod 2
        int hh = lane >> 4, l16 = lane & 15;
        int head = l16 >> 2;                  // head of this lane's channel quad
        float dh = (head == 0) ? d0 : (head == 1) ? d1 : (head == 2) ? d2 : d3;
        float rh = 1.f / (dh + 1e-16f);
        __syncwarp();
        float ax = 0.f, ay = 0.f, az = 0.f, aw = 0.f;
#pragma unroll 4
        for (int i = hh; i < deg; i += 2) {
            int s = col_sh[warp][i];
            float al = ex_sh[warp][i * 4 + head] * rh;
            float4 v = *reinterpret_cast<const float4*>(&g[(size_t)s * 64 + 4 * l16]);
            ax += al * v.x; ay += al * v.y; az += al * v.z; aw += al * v.w;
        }
        ax += __shfl_xor_sync(0xffffffffu, ax, 16);
        ay += __shfl_xor_sync(0xffffffffu, ay, 16);
        az += __shfl_xor_sync(0xffffffffu, az, 16);
        aw += __shfl_xor_sync(0xffffffffu, aw, 16);

        float4 b4 = __ldg(reinterpret_cast<const float4*>(&bias[4 * l16]));
        float h0 = fmaxf(ax + b4.x, 0.f);
        float h1 = fmaxf(ay + b4.y, 0.f);
        float h2 = fmaxf(az + b4.z, 0.f);
        float h3 = fmaxf(aw + b4.w, 0.f);
        if (!FINAL) {
            if (lane < 16) {
                *reinterpret_cast<float4*>(&out1[(size_t)n * 64 + 4 * l16]) =
                    make_float4(h0, h1, h2, h3);
                float dn = dinv[n];
                *reinterpret_cast<float4*>(&out2[(size_t)n * 64 + 4 * l16]) =
                    make_float4(h0 * dn, h1 * dn, h2 * dn, h3 * dn);
            }
        } else {
            float4 w4 = __ldg(reinterpret_cast<const float4*>(&Wl[4 * l16]));
            float p = h0 * w4.x + h1 * w4.y + h2 * w4.z + h3 * w4.w;
#pragma unroll
            for (int o = 8; o; o >>= 1) p += __shfl_xor_sync(0xffffffffu, p, o);
            if (lane == 0) fout[n] = fmaxf(p + __ldg(bl), 0.f);
        }
    } else {
        // fallback: 3-pass global path (rare, degree > 128)
        float m0 = -1e30f, m1 = -1e30f, m2 = -1e30f, m3 = -1e30f;
        for (int i = beg + lane; i < end; i += 32) {
            int s = __ldg(&col[i]);
            float4 as4 = __ldg(reinterpret_cast<const float4*>(&a_s[(size_t)s * 4]));
            m0 = fmaxf(m0, lrelu(as4.x + ad4.x));
            m1 = fmaxf(m1, lrelu(as4.y + ad4.y));
            m2 = fmaxf(m2, lrelu(as4.z + ad4.z));
            m3 = fmaxf(m3, lrelu(as4.w + ad4.w));
        }
#pragma unroll
        for (int o = 16; o; o >>= 1) {
            m0 = fmaxf(m0, __shfl_xor_sync(0xffffffffu, m0, o));
            m1 = fmaxf(m1, __shfl_xor_sync(0xffffffffu, m1, o));
            m2 = fmaxf(m2, __shfl_xor_sync(0xffffffffu, m2, o));
            m3 = fmaxf(m3, __shfl_xor_sync(0xffffffffu, m3, o));
        }
        float d0 = 0.f, d1 = 0.f, d2 = 0.f, d3 = 0.f;
        for (int i = beg + lane; i < end; i += 32) {
            int s = __ldg(&col[i]);
            float4 as4 = __ldg(reinterpret_cast<const float4*>(&a_s[(size_t)s * 4]));
            d0 += __expf(lrelu(as4.x + ad4.x) - m0);
            d1 += __expf(lrelu(as4.y + ad4.y) - m1);
            d2 += __expf(lrelu(as4.z + ad4.z) - m2);
            d3 += __expf(lrelu(as4.w + ad4.w) - m3);
        }
#pragma unroll
        for (int o = 16; o; o >>= 1) {
            d0 += __shfl_xor_sync(0xffffffffu, d0, o);
            d1 += __shfl_xor_sync(0xffffffffu, d1, o);
            d2 += __shfl_xor_sync(0xffffffffu, d2, o);
            d3 += __shfl_xor_sync(0xffffffffu, d3, o);
        }
        float r0 = 1.f / (d0 + 1e-16f), r1 = 1.f / (d1 + 1e-16f);
        float r2 = 1.f / (d2 + 1e-16f), r3 = 1.f / (d3 + 1e-16f);
        int h = lane & 3;
        float mh  = (h == 0) ? m0 : (h == 1) ? m1 : (h == 2) ? m2 : m3;
        float adh = (h == 0) ? ad4.x : (h == 1) ? ad4.y : (h == 2) ? ad4.z : ad4.w;
        float rh  = (h == 0) ? r0 : (h == 1) ? r1 : (h == 2) ? r2 : r3;
        int hsel = lane >> 3;
        float ax = 0.f, ay = 0.f;
        for (int i = beg; i < end; i++) {
            int s = __ldg(&col[i]);
            float asv = __ldg(&a_s[(size_t)s * 4 + h]);
            float al = __expf(lrelu(asv + adh) - mh) * rh;
            float alpha = __shfl_sync(0xffffffffu, al, hsel);
            float2 v2 = *reinterpret_cast<const float2*>(&g[(size_t)s * 64 + 2 * lane]);
            ax += alpha * v2.x;
            ay += alpha * v2.y;
        }
        float2 b2 = __ldg(reinterpret_cast<const float2*>(&bias[2 * lane]));
        float hx = fmaxf(ax + b2.x, 0.f);
        float hy = fmaxf(ay + b2.y, 0.f);
        if (!FINAL) {
            *reinterpret_cast<float2*>(&out1[(size_t)n * 64 + 2 * lane]) = make_float2(hx, hy);
            float dn = dinv[n];
            *reinterpret_cast<float2*>(&out2[(size_t)n * 64 + 2 * lane]) =
                make_float2(hx * dn, hy * dn);
        } else {
            float2 w = __ldg(reinterpret_cast<const float2*>(&Wl[2 * lane]));
            float p = hx * w.x + hy * w.y;
#pragma unroll
            for (int o = 16; o; o >>= 1) p += __shfl_xor_sync(0xffffffffu, p, o);
            if (lane == 0) fout[n] = fmaxf(p + __ldg(bl), 0.f);
        }
    }
}

// ---------------------------------------------------------------------------
// Launch
// ---------------------------------------------------------------------------
extern "C" void kernel_launch(void* const* d_in, const int* in_sizes, int n_in,
                              void* d_out, int out_size) {
    const float* x       = (const float*)d_in[0];
    const int*   ei      = (const int*)d_in[1];
    const float* W1      = (const float*)d_in[2];
    const float* b1      = (const float*)d_in[3];
    const float* W2      = (const float*)d_in[4];
    const float* b2      = (const float*)d_in[5];
    const float* W3      = (const float*)d_in[6];
    const float* b3      = (const float*)d_in[7];
    const float* Wg      = (const float*)d_in[8];
    const float* att_src = (const float*)d_in[9];
    const float* att_dst = (const float*)d_in[10];
    const float* bg      = (const float*)d_in[11];
    const float* Wl      = (const float*)d_in[12];
    const float* bl      = (const float*)d_in[13];
    float* out = (float*)d_out;

    const int* src = ei;
    const int* dst = ei + N_EDGES;

    float *pA, *pB, *pC, *pD, *pAS, *pAD, *pDinv;
    int *pDeg, *pRow, *pCur, *pCol, *pBsum;
    cudaGetSymbolAddress((void**)&pA, g_bufA);
    cudaGetSymbolAddress((void**)&pB, g_bufB);
    cudaGetSymbolAddress((void**)&pC, g_bufC);
    cudaGetSymbolAddress((void**)&pD, g_bufD);
    cudaGetSymbolAddress((void**)&pAS, g_as);
    cudaGetSymbolAddress((void**)&pAD, g_ad);
    cudaGetSymbolAddress((void**)&pDinv, g_dinv);
    cudaGetSymbolAddress((void**)&pDeg, g_deg);
    cudaGetSymbolAddress((void**)&pRow, g_rowptr);
    cudaGetSymbolAddress((void**)&pCur, g_cur);
    cudaGetSymbolAddress((void**)&pCol, g_col);
    cudaGetSymbolAddress((void**)&pBsum, g_bsum);

    const int TB = 256;
    const int gN = (N_NODES + TB - 1) / TB;
    const int gE = (N_EDGES + TB - 1) / TB;
    const int gW = (N_NODES + 7) / 8;     // warp-per-node, 8 warps/block
    const int gF = N_NODES / 32;          // fused transform: 32 nodes/block (3125)

    // ---- build CSR ----
    init_deg_kernel<<<gN, TB>>>(pDeg, N_NODES);
    hist_kernel<<<gE, TB>>>(dst, pDeg, N_EDGES);
    scan1_kernel<<<NB_SCAN, 1024>>>(pDeg, pRow, pBsum, N_NODES);
    scan2_kernel<<<1, 128>>>(pBsum, NB_SCAN);
    csr_init_kernel<<<gN, TB>>>(pRow, pBsum, pDeg, pCur, pCol, pDinv, N_NODES);
    fill_kernel<<<gE, TB>>>(src, dst, pCur, pCol, N_EDGES);

    // ---- layer 1: GCN 128->32 ----
    gemm_l1_kernel<<<gW, TB>>>(x, W1, pDinv, pA, N_NODES);                 // t0
    agg32_kernel<0><<<gW, TB>>>(pA, pRow, pCol, pDinv, b1, pB, N_NODES);   // t1 = h1*dinv

    // ---- layer 2 aggregate (32ch) then fused GEMMs ----
    agg32_kernel<1><<<gW, TB>>>(pB, pRow, pCol, pDinv, nullptr, pA, N_NODES);  // z2
    fused_transform_kernel<32, false><<<gF, TB>>>(pA, nullptr, W2, b2, Wg,
                                                  att_src, att_dst, pC, pAS, pAD);  // g3 + scores

    // ---- layer 3: GAT aggregate ----
    gat_agg_kernel<false><<<gW, TB>>>(pC, pAS, pAD, pRow, pCol, bg, pDinv,
                                      pD, pB, nullptr, nullptr, nullptr, N_NODES);  // h3, t3

    // ---- layer 4 aggregate (64ch) then fused GEMMs (with residual) ----
    agg64_kernel<<<gW, TB>>>(pB, pRow, pCol, pDinv, pA, N_NODES);          // z4
    fused_transform_kernel<64, true><<<gF, TB>>>(pA, pD, W3, b3, Wg,
                                                 att_src, att_dst, pC, pAS, pAD);   // g5 + scores

    // ---- layer 5: GAT aggregate + final projection ----
    gat_agg_kernel<true><<<gW, TB>>>(pC, pAS, pAD, pRow, pCol, bg, pDinv,
                                     nullptr, nullptr, Wl, bl, out, N_NODES);
}

// round 13
// speedup vs baseline: 1.8898x; 1.0478x over previous
#include <cuda_runtime.h>
#include <cuda_fp16.h>
#include <cstdint>

#define N_NODES 100000
#define N_EDGES 1600000
#define E_TOTAL (N_EDGES + N_NODES)   // 1,700,000
#define NB_SCAN ((N_NODES + 1023) / 1024)   // 98

// ---------------------------------------------------------------------------
// Scratch (device globals -- no allocation allowed)
// ---------------------------------------------------------------------------
__device__ int   g_deg[N_NODES];
__device__ int   g_rowptr[N_NODES + 1];
__device__ int   g_cur[N_NODES];
__device__ int   g_col[E_TOTAL];
__device__ int   g_bsum[128];
__device__ float g_dinv[N_NODES];
__device__ float g_bufA[(size_t)N_NODES * 64];
__device__ float g_bufB[(size_t)N_NODES * 64];
__device__ float g_bufC[(size_t)N_NODES * 64];   // g3 (fp32) / g5 (half, reinterpreted)
__device__ float g_bufD[(size_t)N_NODES * 64];
__device__ float g_as[(size_t)N_NODES * 4];
__device__ float g_ad[(size_t)N_NODES * 4];

__device__ __forceinline__ float lrelu(float x) { return x > 0.f ? x : 0.2f * x; }

union F2U { float2 f; unsigned long long u; };
__device__ __forceinline__ float2 ffma2(float2 a, float2 b, float2 c) {
    F2U ua, ub, uc; ua.f = a; ub.f = b; uc.f = c;
    asm("fma.rn.f32x2 %0, %1, %2, %0;" : "+l"(uc.u) : "l"(ua.u), "l"(ub.u));
    return uc.f;
}

// ---------------------------------------------------------------------------
// CSR build (deg zeroed by cudaMemsetAsync; self-loop +1 folded into scan)
// ---------------------------------------------------------------------------
__global__ void hist_kernel(const int* __restrict__ dst, int* __restrict__ deg, int e) {
    int i = blockIdx.x * blockDim.x + threadIdx.x;
    if (i < e) atomicAdd(&deg[dst[i]], 1);
}

// phase 1: per-block exclusive scan of (deg[i]+1), partials + block totals
__global__ void scan1_kernel(const int* __restrict__ deg, int* __restrict__ part,
                             int* __restrict__ bsum, int n) {
    __shared__ int ws[32];
    int tid = threadIdx.x, lane = tid & 31, wid = tid >> 5;
    int i = blockIdx.x * 1024 + tid;
    int v = (i < n) ? deg[i] + 1 : 0;   // +1 = self loop
    int x = v;
#pragma unroll
    for (int o = 1; o < 32; o <<= 1) {
        int t = __shfl_up_sync(0xffffffffu, x, o);
        if (lane >= o) x += t;
    }
    if (lane == 31) ws[wid] = x;
    __syncthreads();
    if (wid == 0) {
        int s = ws[lane];
        int y = s;
#pragma unroll
        for (int o = 1; o < 32; o <<= 1) {
            int t = __shfl_up_sync(0xffffffffu, y, o);
            if (lane >= o) y += t;
        }
        ws[lane] = y - s;
        if (lane == 31) bsum[blockIdx.x] = y;
    }
    __syncthreads();
    if (i < n) part[i] = x - v + ws[wid];
}

// phase 2: exclusive scan of 98 block sums
__global__ void scan2_kernel(int* bsum, int nb) {
    __shared__ int ws[4];
    int tid = threadIdx.x, lane = tid & 31, wid = tid >> 5;
    int v = (tid < nb) ? bsum[tid] : 0;
    int x = v;
#pragma unroll
    for (int o = 1; o < 32; o <<= 1) {
        int t = __shfl_up_sync(0xffffffffu, x, o);
        if (lane >= o) x += t;
    }
    if (lane == 31) ws[wid] = x;
    __syncthreads();
    int off = 0;
    for (int w = 0; w < wid; w++) off += ws[w];
    if (tid < nb) bsum[tid] = x - v + off;
}

// phase 3 fused: finalize rowptr, self-loop slot, cur, dinv
__global__ void csr_init_kernel(int* __restrict__ rowptr, const int* __restrict__ bsum,
                                const int* __restrict__ deg, int* __restrict__ cur,
                                int* __restrict__ col, float* __restrict__ dinv, int n) {
    int i = blockIdx.x * blockDim.x + threadIdx.x;
    if (i >= n) return;
    int r = rowptr[i] + bsum[i >> 10];
    rowptr[i] = r;
    col[r] = i;          // self loop in slot 0
    cur[i] = r + 1;
    dinv[i] = rsqrtf((float)(deg[i] + 1));
    if (i == 0) rowptr[n] = E_TOTAL;
}

__global__ void fill_kernel(const int* __restrict__ src, const int* __restrict__ dst,
                            int* __restrict__ cur, int* __restrict__ col, int e) {
    int i = blockIdx.x * blockDim.x + threadIdx.x;
    if (i >= e) return;
    int p = atomicAdd(&cur[dst[i]], 1);
    col[p] = src[i];
}

// ---------------------------------------------------------------------------
// Layer-1 GEMM: t0 = (x @ W1) * dinv   (128 -> 32, warp-per-node, proven)
// ---------------------------------------------------------------------------
__global__ void gemm_l1_kernel(const float* __restrict__ in, const float* __restrict__ W,
                               const float* __restrict__ dinv, float* __restrict__ out,
                               int n_nodes) {
    __shared__ float Wsh[128 * 32];
    int tid = threadIdx.x;
    for (int i = tid; i < 128 * 32; i += blockDim.x) Wsh[i] = W[i];
    __syncthreads();
    int warp = tid >> 5, lane = tid & 31;
    int n = blockIdx.x * (blockDim.x >> 5) + warp;
    if (n >= n_nodes) return;
    const float4* xr = reinterpret_cast<const float4*>(in + (size_t)n * 128);
    float acc = 0.f;
#pragma unroll
    for (int k4 = 0; k4 < 32; k4++) {
        float4 x4 = __ldg(xr + k4);
        acc += x4.x * Wsh[(4 * k4 + 0) * 32 + lane];
        acc += x4.y * Wsh[(4 * k4 + 1) * 32 + lane];
        acc += x4.z * Wsh[(4 * k4 + 2) * 32 + lane];
        acc += x4.w * Wsh[(4 * k4 + 3) * 32 + lane];
    }
    acc *= dinv[n];
    out[(size_t)n * 32 + lane] = acc;
}

// ---------------------------------------------------------------------------
// 32-channel GCN aggregation: quarter-warp float4 (4 edges in flight/iter)
// MODE 0: out = relu(dinv*acc + b) * dinv      (layer 1)
// MODE 1: out = dinv*acc                       (layer 2 pre-GEMM aggregate)
// ---------------------------------------------------------------------------
template <int MODE>
__global__ void agg32_kernel(const float* __restrict__ t, const int* __restrict__ rowptr,
                             const int* __restrict__ col, const float* __restrict__ dinv,
                             const float* __restrict__ bias, float* __restrict__ out,
                             int n_nodes) {
    int warp = (blockIdx.x * blockDim.x + threadIdx.x) >> 5;
    if (warp >= n_nodes) return;
    int lane = threadIdx.x & 31;
    int q = lane >> 3, l8 = lane & 7;
    int beg = rowptr[warp], end = rowptr[warp + 1];
    float ax = 0.f, ay = 0.f, az = 0.f, aw = 0.f;
#pragma unroll 4
    for (int i = beg + q; i < end; i += 4) {
        int s = __ldg(&col[i]);
        float4 v = *reinterpret_cast<const float4*>(&t[(size_t)s * 32 + 4 * l8]);
        ax += v.x; ay += v.y; az += v.z; aw += v.w;
    }
#pragma unroll
    for (int o = 8; o <= 16; o <<= 1) {
        ax += __shfl_xor_sync(0xffffffffu, ax, o);
        ay += __shfl_xor_sync(0xffffffffu, ay, o);
        az += __shfl_xor_sync(0xffffffffu, az, o);
        aw += __shfl_xor_sync(0xffffffffu, aw, o);
    }
    float dn = dinv[warp];
    if (MODE == 0) {
        float4 bv = __ldg(reinterpret_cast<const float4*>(&bias[4 * l8]));
        ax = fmaxf(dn * ax + bv.x, 0.f) * dn;
        ay = fmaxf(dn * ay + bv.y, 0.f) * dn;
        az = fmaxf(dn * az + bv.z, 0.f) * dn;
        aw = fmaxf(dn * aw + bv.w, 0.f) * dn;
    } else {
        ax *= dn; ay *= dn; az *= dn; aw *= dn;
    }
    if (lane < 8) {
        *reinterpret_cast<float4*>(&out[(size_t)warp * 32 + 4 * l8]) =
            make_float4(ax, ay, az, aw);
    }
}

// ---------------------------------------------------------------------------
// 64-channel GCN pre-aggregate: half-warp float4 (2 edges in flight/iter)
// ---------------------------------------------------------------------------
__global__ void agg64_kernel(const float* __restrict__ t, const int* __restrict__ rowptr,
                             const int* __restrict__ col, const float* __restrict__ dinv,
                             float* __restrict__ out, int n_nodes) {
    int warp = (blockIdx.x * blockDim.x + threadIdx.x) >> 5;
    if (warp >= n_nodes) return;
    int lane = threadIdx.x & 31;
    int h = lane >> 4, l16 = lane & 15;
    int beg = rowptr[warp], end = rowptr[warp + 1];
    float ax = 0.f, ay = 0.f, az = 0.f, aw = 0.f;
#pragma unroll 4
    for (int i = beg + h; i < end; i += 2) {
        int s = __ldg(&col[i]);
        float4 v = *reinterpret_cast<const float4*>(&t[(size_t)s * 64 + 4 * l16]);
        ax += v.x; ay += v.y; az += v.z; aw += v.w;
    }
    ax += __shfl_xor_sync(0xffffffffu, ax, 16);
    ay += __shfl_xor_sync(0xffffffffu, ay, 16);
    az += __shfl_xor_sync(0xffffffffu, az, 16);
    aw += __shfl_xor_sync(0xffffffffu, aw, 16);
    float dn = dinv[warp];
    if (lane < 16) {
        *reinterpret_cast<float4*>(&out[(size_t)warp * 64 + 4 * l16]) =
            make_float4(ax * dn, ay * dn, az * dn, aw * dn);
    }
}

// ---------------------------------------------------------------------------
// Fused transform: h = relu(z @ Wa + ba) [+ hres]; g = h @ Wg; GAT scores.
// GHALF: store g as __half2 (layer 5 only).
// ---------------------------------------------------------------------------
template <int CIN, bool RESID, bool GHALF>
__global__ __launch_bounds__(256) void fused_transform_kernel(
    const float* __restrict__ z, const float* __restrict__ hres,
    const float* __restrict__ Wa, const float* __restrict__ ba,
    const float* __restrict__ Wg, const float* __restrict__ att_s,
    const float* __restrict__ att_d, void* __restrict__ gout,
    float* __restrict__ a_s, float* __restrict__ a_d) {
    __shared__ float Was[CIN * 64];
    __shared__ float Wgs[64 * 64];
    __shared__ float Hs[8][256];
    int tid = threadIdx.x;
    for (int i = tid; i < CIN * 64; i += 256) Was[i] = Wa[i];
    for (int i = tid; i < 64 * 64; i += 256) Wgs[i] = Wg[i];
    __syncthreads();
    int warp = tid >> 5, lane = tid & 31;
    int node0 = blockIdx.x * 32 + warp * 4;

    float2 acc[4];
#pragma unroll
    for (int j = 0; j < 4; j++) acc[j] = make_float2(0.f, 0.f);
    for (int k = 0; k < CIN; k += 4) {
        float2 w0 = *reinterpret_cast<const float2*>(&Was[(k + 0) * 64 + 2 * lane]);
        float2 w1 = *reinterpret_cast<const float2*>(&Was[(k + 1) * 64 + 2 * lane]);
        float2 w2 = *reinterpret_cast<const float2*>(&Was[(k + 2) * 64 + 2 * lane]);
        float2 w3 = *reinterpret_cast<const float2*>(&Was[(k + 3) * 64 + 2 * lane]);
#pragma unroll
        for (int j = 0; j < 4; j++) {
            float4 xv = __ldg(reinterpret_cast<const float4*>(&z[(size_t)(node0 + j) * CIN + k]));
            acc[j] = ffma2(make_float2(xv.x, xv.x), w0, acc[j]);
            acc[j] = ffma2(make_float2(xv.y, xv.y), w1, acc[j]);
            acc[j] = ffma2(make_float2(xv.z, xv.z), w2, acc[j]);
            acc[j] = ffma2(make_float2(xv.w, xv.w), w3, acc[j]);
        }
    }
    float2 bv = __ldg(reinterpret_cast<const float2*>(&ba[2 * lane]));
#pragma unroll
    for (int j = 0; j < 4; j++) {
        float hx = fmaxf(acc[j].x + bv.x, 0.f);
        float hy = fmaxf(acc[j].y + bv.y, 0.f);
        if (RESID) {
            float2 rr = *reinterpret_cast<const float2*>(&hres[(size_t)(node0 + j) * 64 + 2 * lane]);
            hx += rr.x; hy += rr.y;
        }
        *reinterpret_cast<float2*>(&Hs[warp][j * 64 + 2 * lane]) = make_float2(hx, hy);
    }
    __syncwarp();

#pragma unroll
    for (int j = 0; j < 4; j++) acc[j] = make_float2(0.f, 0.f);
    for (int k = 0; k < 64; k += 4) {
        float2 w0 = *reinterpret_cast<const float2*>(&Wgs[(k + 0) * 64 + 2 * lane]);
        float2 w1 = *reinterpret_cast<const float2*>(&Wgs[(k + 1) * 64 + 2 * lane]);
        float2 w2 = *reinterpret_cast<const float2*>(&Wgs[(k + 2) * 64 + 2 * lane]);
        float2 w3 = *reinterpret_cast<const float2*>(&Wgs[(k + 3) * 64 + 2 * lane]);
#pragma unroll
        for (int j = 0; j < 4; j++) {
            float4 hv = *reinterpret_cast<const float4*>(&Hs[warp][j * 64 + k]);
            acc[j] = ffma2(make_float2(hv.x, hv.x), w0, acc[j]);
            acc[j] = ffma2(make_float2(hv.y, hv.y), w1, acc[j]);
            acc[j] = ffma2(make_float2(hv.z, hv.z), w2, acc[j]);
            acc[j] = ffma2(make_float2(hv.w, hv.w), w3, acc[j]);
        }
    }
    float ats0 = __ldg(&att_s[2 * lane]), ats1 = __ldg(&att_s[2 * lane + 1]);
    float atd0 = __ldg(&att_d[2 * lane]), atd1 = __ldg(&att_d[2 * lane + 1]);
#pragma unroll
    for (int j = 0; j < 4; j++) {
        int n = node0 + j;
        float gx = acc[j].x, gy = acc[j].y;
        if (GHALF) {
            reinterpret_cast<__half2*>(gout)[(size_t)n * 32 + lane] = __floats2half2_rn(gx, gy);
        } else {
            reinterpret_cast<float2*>(gout)[(size_t)n * 32 + lane] = make_float2(gx, gy);
        }
        float ps = gx * ats0 + gy * ats1;
        float pd = gx * atd0 + gy * atd1;
#pragma unroll
        for (int o = 1; o < 8; o <<= 1) {
            ps += __shfl_xor_sync(0xffffffffu, ps, o);
            pd += __shfl_xor_sync(0xffffffffu, pd, o);
        }
        if ((lane & 7) == 0) {
            a_s[(size_t)n * 4 + (lane >> 3)] = ps;
            a_d[(size_t)n * 4 + (lane >> 3)] = pd;
        }
    }
}

// ---------------------------------------------------------------------------
// GAT aggregation, no-max softmax (shift-invariant; logits are O(1)):
//   pass 1: gather a_s once, ex = exp(lrelu(e)) into SMEM, accumulate denom
//   pass 2: weighted feature gather, alpha = ex * 1/denom (broadcast LDS)
// GHALF: g is __half (layer 5). FINAL: fused output projection.
// ---------------------------------------------------------------------------
#define GAT_CAP 128

template <bool FINAL, bool GHALF>
__global__ __launch_bounds__(256) void gat_agg_kernel(
    const void* __restrict__ gv, const float* __restrict__ a_s,
    const float* __restrict__ a_d, const int* __restrict__ rowptr,
    const int* __restrict__ col, const float* __restrict__ bias,
    const float* __restrict__ dinv, float* __restrict__ out1,
    float* __restrict__ out2, const float* __restrict__ Wl,
    const float* __restrict__ bl, float* __restrict__ fout, int n_nodes) {
    __shared__ float ex_sh[8][GAT_CAP * 4];   // 16 KB
    __shared__ int   col_sh[8][GAT_CAP];      //  4 KB
    int gwarp = (blockIdx.x * blockDim.x + threadIdx.x) >> 5;
    if (gwarp >= n_nodes) return;
    int warp = threadIdx.x >> 5, lane = threadIdx.x & 31;
    int n = gwarp;
    int beg = rowptr[n], end = rowptr[n + 1];
    int deg = end - beg;
    float4 ad4 = *reinterpret_cast<const float4*>(&a_d[(size_t)n * 4]);
    const float* gf = (const float*)gv;
    const __half* gh = (const __half*)gv;

    if (deg <= GAT_CAP) {
        // pass 1: gather a_s, exp, cache, denom (no max needed)
        float d0 = 0.f, d1 = 0.f, d2 = 0.f, d3 = 0.f;
        for (int i = lane; i < deg; i += 32) {
            int s = __ldg(&col[beg + i]);
            col_sh[warp][i] = s;
            float4 as4 = __ldg(reinterpret_cast<const float4*>(&a_s[(size_t)s * 4]));
            float x0 = __expf(lrelu(as4.x + ad4.x));
            float x1 = __expf(lrelu(as4.y + ad4.y));
            float x2 = __expf(lrelu(as4.z + ad4.z));
            float x3 = __expf(lrelu(as4.w + ad4.w));
            *reinterpret_cast<float4*>(&ex_sh[warp][i * 4]) = make_float4(x0, x1, x2, x3);
            d0 += x0; d1 += x1; d2 += x2; d3 += x3;
        }
#pragma unroll
        for (int o = 16; o; o >>= 1) {
            d0 += __shfl_xor_sync(0xffffffffu, d0, o);
            d1 += __shfl_xor_sync(0xffffffffu, d1, o);
            d2 += __shfl_xor_sync(0xffffffffu, d2, o);
            d3 += __shfl_xor_sync(0xffffffffu, d3, o);
        }
        int hh = lane >> 4, l16 = lane & 15;
        int head = l16 >> 2;
        float dh = (head == 0) ? d0 : (head == 1) ? d1 : (head == 2) ? d2 : d3;
        float rh = 1.f / (dh + 1e-16f);
        __syncwarp();
        // pass 2: weighted gather (half-warp, 2 edges in flight)
        float ax = 0.f, ay = 0.f, az = 0.f, aw = 0.f;
#pragma unroll 4
        for (int i = hh; i < deg; i += 2) {
            int s = col_sh[warp][i];
            float al = ex_sh[warp][i * 4 + head] * rh;
            if (GHALF) {
                uint2 raw = *reinterpret_cast<const uint2*>(gh + (size_t)s * 64 + 4 * l16);
                float2 f0 = __half22float2(*reinterpret_cast<__half2*>(&raw.x));
                float2 f1 = __half22float2(*reinterpret_cast<__half2*>(&raw.y));
                ax += al * f0.x; ay += al * f0.y; az += al * f1.x; aw += al * f1.y;
            } else {
                float4 v = *reinterpret_cast<const float4*>(&gf[(size_t)s * 64 + 4 * l16]);
                ax += al * v.x; ay += al * v.y; az += al * v.z; aw += al * v.w;
            }
        }
        ax += __shfl_xor_sync(0xffffffffu, ax, 16);
        ay += __shfl_xor_sync(0xffffffffu, ay, 16);
        az += __shfl_xor_sync(0xffffffffu, az, 16);
        aw += __shfl_xor_sync(0xffffffffu, aw, 16);

        float4 b4 = __ldg(reinterpret_cast<const float4*>(&bias[4 * l16]));
        float h0 = fmaxf(ax + b4.x, 0.f);
        float h1 = fmaxf(ay + b4.y, 0.f);
        float h2 = fmaxf(az + b4.z, 0.f);
        float h3 = fmaxf(aw + b4.w, 0.f);
        if (!FINAL) {
            if (lane < 16) {
                *reinterpret_cast<float4*>(&out1[(size_t)n * 64 + 4 * l16]) =
                    make_float4(h0, h1, h2, h3);
                float dn = dinv[n];
                *reinterpret_cast<float4*>(&out2[(size_t)n * 64 + 4 * l16]) =
                    make_float4(h0 * dn, h1 * dn, h2 * dn, h3 * dn);
            }
        } else {
            float4 w4 = __ldg(reinterpret_cast<const float4*>(&Wl[4 * l16]));
            float p = h0 * w4.x + h1 * w4.y + h2 * w4.z + h3 * w4.w;
#pragma unroll
            for (int o = 8; o; o >>= 1) p += __shfl_xor_sync(0xffffffffu, p, o);
            if (lane == 0) fout[n] = fmaxf(p + __ldg(bl), 0.f);
        }
    } else {
        // fallback for degree > 128 (rare): 2-pass global, no max
        float d0 = 0.f, d1 = 0.f, d2 = 0.f, d3 = 0.f;
        for (int i = beg + lane; i < end; i += 32) {
            int s = __ldg(&col[i]);
            float4 as4 = __ldg(reinterpret_cast<const float4*>(&a_s[(size_t)s * 4]));
            d0 += __expf(lrelu(as4.x + ad4.x));
            d1 += __expf(lrelu(as4.y + ad4.y));
            d2 += __expf(lrelu(as4.z + ad4.z));
            d3 += __expf(lrelu(as4.w + ad4.w));
        }
#pragma unroll
        for (int o = 16; o; o >>= 1) {
            d0 += __shfl_xor_sync(0xffffffffu, d0, o);
            d1 += __shfl_xor_sync(0xffffffffu, d1, o);
            d2 += __shfl_xor_sync(0xffffffffu, d2, o);
            d3 += __shfl_xor_sync(0xffffffffu, d3, o);
        }
        float r0 = 1.f / (d0 + 1e-16f), r1 = 1.f / (d1 + 1e-16f);
        float r2 = 1.f / (d2 + 1e-16f), r3 = 1.f / (d3 + 1e-16f);
        int h = lane & 3;
        float adh = (h == 0) ? ad4.x : (h == 1) ? ad4.y : (h == 2) ? ad4.z : ad4.w;
        float rh  = (h == 0) ? r0 : (h == 1) ? r1 : (h == 2) ? r2 : r3;
        int hsel = lane >> 3;
        float ax = 0.f, ay = 0.f;
        for (int i = beg; i < end; i++) {
            int s = __ldg(&col[i]);
            float asv = __ldg(&a_s[(size_t)s * 4 + h]);
            float al = __expf(lrelu(asv + adh)) * rh;
            float alpha = __shfl_sync(0xffffffffu, al, hsel);
            float vx, vy;
            if (GHALF) {
                float2 f = __half22float2(
                    *reinterpret_cast<const __half2*>(gh + (size_t)s * 64 + 2 * lane));
                vx = f.x; vy = f.y;
            } else {
                float2 v2 = *reinterpret_cast<const float2*>(&gf[(size_t)s * 64 + 2 * lane]);
                vx = v2.x; vy = v2.y;
            }
            ax += alpha * vx;
            ay += alpha * vy;
        }
        float2 b2 = __ldg(reinterpret_cast<const float2*>(&bias[2 * lane]));
        float hx = fmaxf(ax + b2.x, 0.f);
        float hy = fmaxf(ay + b2.y, 0.f);
        if (!FINAL) {
            *reinterpret_cast<float2*>(&out1[(size_t)n * 64 + 2 * lane]) = make_float2(hx, hy);
            float dn = dinv[n];
            *reinterpret_cast<float2*>(&out2[(size_t)n * 64 + 2 * lane]) =
                make_float2(hx * dn, hy * dn);
        } else {
            float2 w = __ldg(reinterpret_cast<const float2*>(&Wl[2 * lane]));
            float p = hx * w.x + hy * w.y;
#pragma unroll
            for (int o = 16; o; o >>= 1) p += __shfl_xor_sync(0xffffffffu, p, o);
            if (lane == 0) fout[n] = fmaxf(p + __ldg(bl), 0.f);
        }
    }
}

// ---------------------------------------------------------------------------
// Launch
// ---------------------------------------------------------------------------
extern "C" void kernel_launch(void* const* d_in, const int* in_sizes, int n_in,
                              void* d_out, int out_size) {
    const float* x       = (const float*)d_in[0];
    const int*   ei      = (const int*)d_in[1];
    const float* W1      = (const float*)d_in[2];
    const float* b1      = (const float*)d_in[3];
    const float* W2      = (const float*)d_in[4];
    const float* b2      = (const float*)d_in[5];
    const float* W3      = (const float*)d_in[6];
    const float* b3      = (const float*)d_in[7];
    const float* Wg      = (const float*)d_in[8];
    const float* att_src = (const float*)d_in[9];
    const float* att_dst = (const float*)d_in[10];
    const float* bg      = (const float*)d_in[11];
    const float* Wl      = (const float*)d_in[12];
    const float* bl      = (const float*)d_in[13];
    float* out = (float*)d_out;

    const int* src = ei;
    const int* dst = ei + N_EDGES;

    float *pA, *pB, *pC, *pD, *pAS, *pAD, *pDinv;
    int *pDeg, *pRow, *pCur, *pCol, *pBsum;
    cudaGetSymbolAddress((void**)&pA, g_bufA);
    cudaGetSymbolAddress((void**)&pB, g_bufB);
    cudaGetSymbolAddress((void**)&pC, g_bufC);
    cudaGetSymbolAddress((void**)&pD, g_bufD);
    cudaGetSymbolAddress((void**)&pAS, g_as);
    cudaGetSymbolAddress((void**)&pAD, g_ad);
    cudaGetSymbolAddress((void**)&pDinv, g_dinv);
    cudaGetSymbolAddress((void**)&pDeg, g_deg);
    cudaGetSymbolAddress((void**)&pRow, g_rowptr);
    cudaGetSymbolAddress((void**)&pCur, g_cur);
    cudaGetSymbolAddress((void**)&pCol, g_col);
    cudaGetSymbolAddress((void**)&pBsum, g_bsum);

    const int TB = 256;
    const int gN = (N_NODES + TB - 1) / TB;
    const int gE = (N_EDGES + TB - 1) / TB;
    const int gW = (N_NODES + 7) / 8;     // warp-per-node, 8 warps/block
    const int gF = N_NODES / 32;          // fused transform: 32 nodes/block (3125)

    // ---- build CSR ----
    cudaMemsetAsync(pDeg, 0, N_NODES * sizeof(int));
    hist_kernel<<<gE, TB>>>(dst, pDeg, N_EDGES);
    scan1_kernel<<<NB_SCAN, 1024>>>(pDeg, pRow, pBsum, N_NODES);
    scan2_kernel<<<1, 128>>>(pBsum, NB_SCAN);
    csr_init_kernel<<<gN, TB>>>(pRow, pBsum, pDeg, pCur, pCol, pDinv, N_NODES);
    fill_kernel<<<gE, TB>>>(src, dst, pCur, pCol, N_EDGES);

    // ---- layer 1: GCN 128->32 ----
    gemm_l1_kernel<<<gW, TB>>>(x, W1, pDinv, pA, N_NODES);                 // t0
    agg32_kernel<0><<<gW, TB>>>(pA, pRow, pCol, pDinv, b1, pB, N_NODES);   // t1 = h1*dinv

    // ---- layer 2 aggregate (32ch) then fused GEMMs ----
    agg32_kernel<1><<<gW, TB>>>(pB, pRow, pCol, pDinv, nullptr, pA, N_NODES);  // z2
    fused_transform_kernel<32, false, false><<<gF, TB>>>(pA, nullptr, W2, b2, Wg,
                                                         att_src, att_dst, pC, pAS, pAD);

    // ---- layer 3: GAT aggregate (fp32 g3) ----
    gat_agg_kernel<false, false><<<gW, TB>>>(pC, pAS, pAD, pRow, pCol, bg, pDinv,
                                             pD, pB, nullptr, nullptr, nullptr, N_NODES);

    // ---- layer 4 aggregate (64ch) then fused GEMMs (residual, g5 in half) ----
    agg64_kernel<<<gW, TB>>>(pB, pRow, pCol, pDinv, pA, N_NODES);          // z4
    fused_transform_kernel<64, true, true><<<gF, TB>>>(pA, pD, W3, b3, Wg,
                                                       att_src, att_dst, pC, pAS, pAD);

    // ---- layer 5: GAT aggregate (half g5) + final projection ----
    gat_agg_kernel<true, true><<<gW, TB>>>(pC, pAS, pAD, pRow, pCol, bg, pDinv,
                                           nullptr, nullptr, Wl, bl, out, N_NODES);
}

// round 15
// speedup vs baseline: 1.9616x; 1.0380x over previous
#include <cuda_runtime.h>
#include <cuda_fp16.h>
#include <cstdint>

#define N_NODES 100000
#define N_EDGES 1600000
#define E_TOTAL (N_EDGES + N_NODES)   // 1,700,000
#define NB_SCAN ((N_NODES + 1023) / 1024)   // 98

// ---------------------------------------------------------------------------
// Scratch (device globals -- no allocation allowed)
// ---------------------------------------------------------------------------
__device__ int   g_deg[N_NODES];
__device__ int   g_rowptr[N_NODES + 1];
__device__ int   g_cur[N_NODES];
__device__ int   g_col[E_TOTAL];
__device__ int   g_bsum[128];
__device__ float g_dinv[N_NODES];
__device__ float g_bufA[(size_t)N_NODES * 64];
__device__ float g_bufB[(size_t)N_NODES * 64];   // t3 (half, reinterpreted) etc.
__device__ float g_bufC[(size_t)N_NODES * 64];   // g3 / g5 (half, reinterpreted)
__device__ float g_bufD[(size_t)N_NODES * 64];
__device__ float g_as[(size_t)N_NODES * 4];
__device__ float g_ad[(size_t)N_NODES * 4];

__device__ __forceinline__ float lrelu(float x) { return x > 0.f ? x : 0.2f * x; }

union F2U { float2 f; unsigned long long u; };
__device__ __forceinline__ float2 ffma2(float2 a, float2 b, float2 c) {
    F2U ua, ub, uc; ua.f = a; ub.f = b; uc.f = c;
    asm("fma.rn.f32x2 %0, %1, %2, %0;" : "+l"(uc.u) : "l"(ua.u), "l"(ub.u));
    return uc.f;
}

// ---------------------------------------------------------------------------
// CSR build (deg zeroed by cudaMemsetAsync; self-loop +1 folded into scan)
// ---------------------------------------------------------------------------
__global__ void hist_kernel(const int* __restrict__ dst, int* __restrict__ deg, int e) {
    int i = blockIdx.x * blockDim.x + threadIdx.x;
    if (i < e) atomicAdd(&deg[dst[i]], 1);
}

__global__ void scan1_kernel(const int* __restrict__ deg, int* __restrict__ part,
                             int* __restrict__ bsum, int n) {
    __shared__ int ws[32];
    int tid = threadIdx.x, lane = tid & 31, wid = tid >> 5;
    int i = blockIdx.x * 1024 + tid;
    int v = (i < n) ? deg[i] + 1 : 0;   // +1 = self loop
    int x = v;
#pragma unroll
    for (int o = 1; o < 32; o <<= 1) {
        int t = __shfl_up_sync(0xffffffffu, x, o);
        if (lane >= o) x += t;
    }
    if (lane == 31) ws[wid] = x;
    __syncthreads();
    if (wid == 0) {
        int s = ws[lane];
        int y = s;
#pragma unroll
        for (int o = 1; o < 32; o <<= 1) {
            int t = __shfl_up_sync(0xffffffffu, y, o);
            if (lane >= o) y += t;
        }
        ws[lane] = y - s;
        if (lane == 31) bsum[blockIdx.x] = y;
    }
    __syncthreads();
    if (i < n) part[i] = x - v + ws[wid];
}

__global__ void scan2_kernel(int* bsum, int nb) {
    __shared__ int ws[4];
    int tid = threadIdx.x, lane = tid & 31, wid = tid >> 5;
    int v = (tid < nb) ? bsum[tid] : 0;
    int x = v;
#pragma unroll
    for (int o = 1; o < 32; o <<= 1) {
        int t = __shfl_up_sync(0xffffffffu, x, o);
        if (lane >= o) x += t;
    }
    if (lane == 31) ws[wid] = x;
    __syncthreads();
    int off = 0;
    for (int w = 0; w < wid; w++) off += ws[w];
    if (tid < nb) bsum[tid] = x - v + off;
}

__global__ void csr_init_kernel(int* __restrict__ rowptr, const int* __restrict__ bsum,
                                const int* __restrict__ deg, int* __restrict__ cur,
                                int* __restrict__ col, float* __restrict__ dinv, int n) {
    int i = blockIdx.x * blockDim.x + threadIdx.x;
    if (i >= n) return;
    int r = rowptr[i] + bsum[i >> 10];
    rowptr[i] = r;
    col[r] = i;          // self loop in slot 0
    cur[i] = r + 1;
    dinv[i] = rsqrtf((float)(deg[i] + 1));
    if (i == 0) rowptr[n] = E_TOTAL;
}

__global__ void fill_kernel(const int* __restrict__ src, const int* __restrict__ dst,
                            int* __restrict__ cur, int* __restrict__ col, int e) {
    int i = blockIdx.x * blockDim.x + threadIdx.x;
    if (i >= e) return;
    int p = atomicAdd(&cur[dst[i]], 1);
    col[p] = src[i];
}

// ---------------------------------------------------------------------------
// Layer-1 GEMM: t0 = (x @ W1) * dinv   (128 -> 32, warp-per-node, proven)
// ---------------------------------------------------------------------------
__global__ void gemm_l1_kernel(const float* __restrict__ in, const float* __restrict__ W,
                               const float* __restrict__ dinv, float* __restrict__ out,
                               int n_nodes) {
    __shared__ float Wsh[128 * 32];
    int tid = threadIdx.x;
    for (int i = tid; i < 128 * 32; i += blockDim.x) Wsh[i] = W[i];
    __syncthreads();
    int warp = tid >> 5, lane = tid & 31;
    int n = blockIdx.x * (blockDim.x >> 5) + warp;
    if (n >= n_nodes) return;
    const float4* xr = reinterpret_cast<const float4*>(in + (size_t)n * 128);
    float acc = 0.f;
#pragma unroll
    for (int k4 = 0; k4 < 32; k4++) {
        float4 x4 = __ldg(xr + k4);
        acc += x4.x * Wsh[(4 * k4 + 0) * 32 + lane];
        acc += x4.y * Wsh[(4 * k4 + 1) * 32 + lane];
        acc += x4.z * Wsh[(4 * k4 + 2) * 32 + lane];
        acc += x4.w * Wsh[(4 * k4 + 3) * 32 + lane];
    }
    acc *= dinv[n];
    out[(size_t)n * 32 + lane] = acc;
}

// ---------------------------------------------------------------------------
// 32-channel GCN aggregation: quarter-warp float4 (4 edges in flight/iter)
// MODE 0: out = relu(dinv*acc + b) * dinv      (layer 1)
// MODE 1: out = dinv*acc                       (layer 2 pre-GEMM aggregate)
// ---------------------------------------------------------------------------
template <int MODE>
__global__ void agg32_kernel(const float* __restrict__ t, const int* __restrict__ rowptr,
                             const int* __restrict__ col, const float* __restrict__ dinv,
                             const float* __restrict__ bias, float* __restrict__ out,
                             int n_nodes) {
    int warp = (blockIdx.x * blockDim.x + threadIdx.x) >> 5;
    if (warp >= n_nodes) return;
    int lane = threadIdx.x & 31;
    int q = lane >> 3, l8 = lane & 7;
    int beg = rowptr[warp], end = rowptr[warp + 1];
    float ax = 0.f, ay = 0.f, az = 0.f, aw = 0.f;
#pragma unroll 4
    for (int i = beg + q; i < end; i += 4) {
        int s = __ldg(&col[i]);
        float4 v = *reinterpret_cast<const float4*>(&t[(size_t)s * 32 + 4 * l8]);
        ax += v.x; ay += v.y; az += v.z; aw += v.w;
    }
#pragma unroll
    for (int o = 8; o <= 16; o <<= 1) {
        ax += __shfl_xor_sync(0xffffffffu, ax, o);
        ay += __shfl_xor_sync(0xffffffffu, ay, o);
        az += __shfl_xor_sync(0xffffffffu, az, o);
        aw += __shfl_xor_sync(0xffffffffu, aw, o);
    }
    float dn = dinv[warp];
    if (MODE == 0) {
        float4 bv = __ldg(reinterpret_cast<const float4*>(&bias[4 * l8]));
        ax = fmaxf(dn * ax + bv.x, 0.f) * dn;
        ay = fmaxf(dn * ay + bv.y, 0.f) * dn;
        az = fmaxf(dn * az + bv.z, 0.f) * dn;
        aw = fmaxf(dn * aw + bv.w, 0.f) * dn;
    } else {
        ax *= dn; ay *= dn; az *= dn; aw *= dn;
    }
    if (lane < 8) {
        *reinterpret_cast<float4*>(&out[(size_t)warp * 32 + 4 * l8]) =
            make_float4(ax, ay, az, aw);
    }
}

// ---------------------------------------------------------------------------
// 64-channel GCN pre-aggregate from HALF input: z = dinv * sum t[s] (layer 4)
// half-warp, 8-byte loads (4 half), 2 edges in flight/iter
// ---------------------------------------------------------------------------
__global__ void agg64h_kernel(const __half* __restrict__ t, const int* __restrict__ rowptr,
                              const int* __restrict__ col, const float* __restrict__ dinv,
                              float* __restrict__ out, int n_nodes) {
    int warp = (blockIdx.x * blockDim.x + threadIdx.x) >> 5;
    if (warp >= n_nodes) return;
    int lane = threadIdx.x & 31;
    int h = lane >> 4, l16 = lane & 15;
    int beg = rowptr[warp], end = rowptr[warp + 1];
    float ax = 0.f, ay = 0.f, az = 0.f, aw = 0.f;
#pragma unroll 4
    for (int i = beg + h; i < end; i += 2) {
        int s = __ldg(&col[i]);
        uint2 raw = *reinterpret_cast<const uint2*>(t + (size_t)s * 64 + 4 * l16);
        float2 f0 = __half22float2(*reinterpret_cast<__half2*>(&raw.x));
        float2 f1 = __half22float2(*reinterpret_cast<__half2*>(&raw.y));
        ax += f0.x; ay += f0.y; az += f1.x; aw += f1.y;
    }
    ax += __shfl_xor_sync(0xffffffffu, ax, 16);
    ay += __shfl_xor_sync(0xffffffffu, ay, 16);
    az += __shfl_xor_sync(0xffffffffu, az, 16);
    aw += __shfl_xor_sync(0xffffffffu, aw, 16);
    float dn = dinv[warp];
    if (lane < 16) {
        *reinterpret_cast<float4*>(&out[(size_t)warp * 64 + 4 * l16]) =
            make_float4(ax * dn, ay * dn, az * dn, aw * dn);
    }
}

// ---------------------------------------------------------------------------
// Fused transform: h = relu(z @ Wa + ba) [+ hres]; g = h @ Wg; GAT scores.
// g always emitted as __half2 (both GAT layers now consume half features).
// Scores computed from fp32 accumulators (unaffected by payload rounding).
// ---------------------------------------------------------------------------
template <int CIN, bool RESID>
__global__ __launch_bounds__(256) void fused_transform_kernel(
    const float* __restrict__ z, const float* __restrict__ hres,
    const float* __restrict__ Wa, const float* __restrict__ ba,
    const float* __restrict__ Wg, const float* __restrict__ att_s,
    const float* __restrict__ att_d, __half2* __restrict__ gout,
    float* __restrict__ a_s, float* __restrict__ a_d) {
    __shared__ float Was[CIN * 64];
    __shared__ float Wgs[64 * 64];
    __shared__ float Hs[8][256];
    int tid = threadIdx.x;
    for (int i = tid; i < CIN * 64; i += 256) Was[i] = Wa[i];
    for (int i = tid; i < 64 * 64; i += 256) Wgs[i] = Wg[i];
    __syncthreads();
    int warp = tid >> 5, lane = tid & 31;
    int node0 = blockIdx.x * 32 + warp * 4;

    float2 acc[4];
#pragma unroll
    for (int j = 0; j < 4; j++) acc[j] = make_float2(0.f, 0.f);
    for (int k = 0; k < CIN; k += 4) {
        float2 w0 = *reinterpret_cast<const float2*>(&Was[(k + 0) * 64 + 2 * lane]);
        float2 w1 = *reinterpret_cast<const float2*>(&Was[(k + 1) * 64 + 2 * lane]);
        float2 w2 = *reinterpret_cast<const float2*>(&Was[(k + 2) * 64 + 2 * lane]);
        float2 w3 = *reinterpret_cast<const float2*>(&Was[(k + 3) * 64 + 2 * lane]);
#pragma unroll
        for (int j = 0; j < 4; j++) {
            float4 xv = __ldg(reinterpret_cast<const float4*>(&z[(size_t)(node0 + j) * CIN + k]));
            acc[j] = ffma2(make_float2(xv.x, xv.x), w0, acc[j]);
            acc[j] = ffma2(make_float2(xv.y, xv.y), w1, acc[j]);
            acc[j] = ffma2(make_float2(xv.z, xv.z), w2, acc[j]);
            acc[j] = ffma2(make_float2(xv.w, xv.w), w3, acc[j]);
        }
    }
    float2 bv = __ldg(reinterpret_cast<const float2*>(&ba[2 * lane]));
#pragma unroll
    for (int j = 0; j < 4; j++) {
        float hx = fmaxf(acc[j].x + bv.x, 0.f);
        float hy = fmaxf(acc[j].y + bv.y, 0.f);
        if (RESID) {
            float2 rr = *reinterpret_cast<const float2*>(&hres[(size_t)(node0 + j) * 64 + 2 * lane]);
            hx += rr.x; hy += rr.y;
        }
        *reinterpret_cast<float2*>(&Hs[warp][j * 64 + 2 * lane]) = make_float2(hx, hy);
    }
    __syncwarp();

#pragma unroll
    for (int j = 0; j < 4; j++) acc[j] = make_float2(0.f, 0.f);
    for (int k = 0; k < 64; k += 4) {
        float2 w0 = *reinterpret_cast<const float2*>(&Wgs[(k + 0) * 64 + 2 * lane]);
        float2 w1 = *reinterpret_cast<const float2*>(&Wgs[(k + 1) * 64 + 2 * lane]);
        float2 w2 = *reinterpret_cast<const float2*>(&Wgs[(k + 2) * 64 + 2 * lane]);
        float2 w3 = *reinterpret_cast<const float2*>(&Wgs[(k + 3) * 64 + 2 * lane]);
#pragma unroll
        for (int j = 0; j < 4; j++) {
            float4 hv = *reinterpret_cast<const float4*>(&Hs[warp][j * 64 + k]);
            acc[j] = ffma2(make_float2(hv.x, hv.x), w0, acc[j]);
            acc[j] = ffma2(make_float2(hv.y, hv.y), w1, acc[j]);
            acc[j] = ffma2(make_float2(hv.z, hv.z), w2, acc[j]);
            acc[j] = ffma2(make_float2(hv.w, hv.w), w3, acc[j]);
        }
    }
    float ats0 = __ldg(&att_s[2 * lane]), ats1 = __ldg(&att_s[2 * lane + 1]);
    float atd0 = __ldg(&att_d[2 * lane]), atd1 = __ldg(&att_d[2 * lane + 1]);
#pragma unroll
    for (int j = 0; j < 4; j++) {
        int n = node0 + j;
        float gx = acc[j].x, gy = acc[j].y;
        gout[(size_t)n * 32 + lane] = __floats2half2_rn(gx, gy);
        float ps = gx * ats0 + gy * ats1;
        float pd = gx * atd0 + gy * atd1;
#pragma unroll
        for (int o = 1; o < 8; o <<= 1) {
            ps += __shfl_xor_sync(0xffffffffu, ps, o);
            pd += __shfl_xor_sync(0xffffffffu, pd, o);
        }
        if ((lane & 7) == 0) {
            a_s[(size_t)n * 4 + (lane >> 3)] = ps;
            a_d[(size_t)n * 4 + (lane >> 3)] = pd;
        }
    }
}

// ---------------------------------------------------------------------------
// GAT aggregation, no-max softmax, half feature payload:
//   pass 1: gather a_s once, ex = exp(lrelu(e)) into SMEM, accumulate denom
//   pass 2: weighted half-feature gather, alpha from SMEM
// FINAL=false: out1 = relu(agg+bias) fp32 (residual), out2 = out1*dinv HALF (t3)
// FINAL=true : fout[n] = relu(<relu(agg+bias), Wl> + bl)
// ---------------------------------------------------------------------------
#define GAT_CAP 128

template <bool FINAL>
__global__ __launch_bounds__(256) void gat_agg_kernel(
    const __half* __restrict__ gh, const float* __restrict__ a_s,
    const float* __restrict__ a_d, const int* __restrict__ rowptr,
    const int* __restrict__ col, const float* __restrict__ bias,
    const float* __restrict__ dinv, float* __restrict__ out1,
    __half2* __restrict__ out2, const float* __restrict__ Wl,
    const float* __restrict__ bl, float* __restrict__ fout, int n_nodes) {
    __shared__ float ex_sh[8][GAT_CAP * 4];   // 16 KB
    __shared__ int   col_sh[8][GAT_CAP];      //  4 KB
    int gwarp = (blockIdx.x * blockDim.x + threadIdx.x) >> 5;
    if (gwarp >= n_nodes) return;
    int warp = threadIdx.x >> 5, lane = threadIdx.x & 31;
    int n = gwarp;
    int beg = rowptr[n], end = rowptr[n + 1];
    int deg = end - beg;
    float4 ad4 = *reinterpret_cast<const float4*>(&a_d[(size_t)n * 4]);

    if (deg <= GAT_CAP) {
        float d0 = 0.f, d1 = 0.f, d2 = 0.f, d3 = 0.f;
        for (int i = lane; i < deg; i += 32) {
            int s = __ldg(&col[beg + i]);
            col_sh[warp][i] = s;
            float4 as4 = __ldg(reinterpret_cast<const float4*>(&a_s[(size_t)s * 4]));
            float x0 = __expf(lrelu(as4.x + ad4.x));
            float x1 = __expf(lrelu(as4.y + ad4.y));
            float x2 = __expf(lrelu(as4.z + ad4.z));
            float x3 = __expf(lrelu(as4.w + ad4.w));
            *reinterpret_cast<float4*>(&ex_sh[warp][i * 4]) = make_float4(x0, x1, x2, x3);
            d0 += x0; d1 += x1; d2 += x2; d3 += x3;
        }
#pragma unroll
        for (int o = 16; o; o >>= 1) {
            d0 += __shfl_xor_sync(0xffffffffu, d0, o);
            d1 += __shfl_xor_sync(0xffffffffu, d1, o);
            d2 += __shfl_xor_sync(0xffffffffu, d2, o);
            d3 += __shfl_xor_sync(0xffffffffu, d3, o);
        }
        int hh = lane >> 4, l16 = lane & 15;
        int head = l16 >> 2;
        float dh = (head == 0) ? d0 : (head == 1) ? d1 : (head == 2) ? d2 : d3;
        float rh = 1.f / (dh + 1e-16f);
        __syncwarp();
        float ax = 0.f, ay = 0.f, az = 0.f, aw = 0.f;
#pragma unroll 4
        for (int i = hh; i < deg; i += 2) {
            int s = col_sh[warp][i];
            float al = ex_sh[warp][i * 4 + head] * rh;
            uint2 raw = *reinterpret_cast<const uint2*>(gh + (size_t)s * 64 + 4 * l16);
            float2 f0 = __half22float2(*reinterpret_cast<__half2*>(&raw.x));
            float2 f1 = __half22float2(*reinterpret_cast<__half2*>(&raw.y));
            ax += al * f0.x; ay += al * f0.y; az += al * f1.x; aw += al * f1.y;
        }
        ax += __shfl_xor_sync(0xffffffffu, ax, 16);
        ay += __shfl_xor_sync(0xffffffffu, ay, 16);
        az += __shfl_xor_sync(0xffffffffu, az, 16);
        aw += __shfl_xor_sync(0xffffffffu, aw, 16);

        float4 b4 = __ldg(reinterpret_cast<const float4*>(&bias[4 * l16]));
        float h0 = fmaxf(ax + b4.x, 0.f);
        float h1 = fmaxf(ay + b4.y, 0.f);
        float h2 = fmaxf(az + b4.z, 0.f);
        float h3 = fmaxf(aw + b4.w, 0.f);
        if (!FINAL) {
            if (lane < 16) {
                *reinterpret_cast<float4*>(&out1[(size_t)n * 64 + 4 * l16]) =
                    make_float4(h0, h1, h2, h3);
                float dn = dinv[n];
                uint2 pk;
                __half2 p0 = __floats2half2_rn(h0 * dn, h1 * dn);
                __half2 p1 = __floats2half2_rn(h2 * dn, h3 * dn);
                pk.x = *reinterpret_cast<unsigned*>(&p0);
                pk.y = *reinterpret_cast<unsigned*>(&p1);
                *reinterpret_cast<uint2*>(&out2[(size_t)n * 32 + 2 * l16]) = pk;
            }
        } else {
            float4 w4 = __ldg(reinterpret_cast<const float4*>(&Wl[4 * l16]));
            float p = h0 * w4.x + h1 * w4.y + h2 * w4.z + h3 * w4.w;
#pragma unroll
            for (int o = 8; o; o >>= 1) p += __shfl_xor_sync(0xffffffffu, p, o);
            if (lane == 0) fout[n] = fmaxf(p + __ldg(bl), 0.f);
        }
    } else {
        // fallback for degree > 128 (rare): 2-pass global, no max
        float d0 = 0.f, d1 = 0.f, d2 = 0.f, d3 = 0.f;
        for (int i = beg + lane; i < end; i += 32) {
            int s = __ldg(&col[i]);
            float4 as4 = __ldg(reinterpret_cast<const float4*>(&a_s[(size_t)s * 4]));
            d0 += __expf(lrelu(as4.x + ad4.x));
            d1 += __expf(lrelu(as4.y + ad4.y));
            d2 += __expf(lrelu(as4.z + ad4.z));
            d3 += __expf(lrelu(as4.w + ad4.w));
        }
#pragma unroll
        for (int o = 16; o; o >>= 1) {
            d0 += __shfl_xor_sync(0xffffffffu, d0, o);
            d1 += __shfl_xor_sync(0xffffffffu, d1, o);
            d2 += __shfl_xor_sync(0xffffffffu, d2, o);
            d3 += __shfl_xor_sync(0xffffffffu, d3, o);
        }
        float r0 = 1.f / (d0 + 1e-16f), r1 = 1.f / (d1 + 1e-16f);
        float r2 = 1.f / (d2 + 1e-16f), r3 = 1.f / (d3 + 1e-16f);
        int h = lane & 3;
        float adh = (h == 0) ? ad4.x : (h == 1) ? ad4.y : (h == 2) ? ad4.z : ad4.w;
        float rh  = (h == 0) ? r0 : (h == 1) ? r1 : (h == 2) ? r2 : r3;
        int hsel = lane >> 3;
        float ax = 0.f, ay = 0.f;
        for (int i = beg; i < end; i++) {
            int s = __ldg(&col[i]);
            float asv = __ldg(&a_s[(size_t)s * 4 + h]);
            float al = __expf(lrelu(asv + adh)) * rh;
            float alpha = __shfl_sync(0xffffffffu, al, hsel);
            float2 f = __half22float2(
                *reinterpret_cast<const __half2*>(gh + (size_t)s * 64 + 2 * lane));
            ax += alpha * f.x;
            ay += alpha * f.y;
        }
        float2 b2 = __ldg(reinterpret_cast<const float2*>(&bias[2 * lane]));
        float hx = fmaxf(ax + b2.x, 0.f);
        float hy = fmaxf(ay + b2.y, 0.f);
        if (!FINAL) {
            *reinterpret_cast<float2*>(&out1[(size_t)n * 64 + 2 * lane]) = make_float2(hx, hy);
            float dn = dinv[n];
            out2[(size_t)n * 32 + lane] = __floats2half2_rn(hx * dn, hy * dn);
        } else {
            float2 w = __ldg(reinterpret_cast<const float2*>(&Wl[2 * lane]));
            float p = hx * w.x + hy * w.y;
#pragma unroll
            for (int o = 16; o; o >>= 1) p += __shfl_xor_sync(0xffffffffu, p, o);
            if (lane == 0) fout[n] = fmaxf(p + __ldg(bl), 0.f);
        }
    }
}

// ---------------------------------------------------------------------------
// Launch
// ---------------------------------------------------------------------------
extern "C" void kernel_launch(void* const* d_in, const int* in_sizes, int n_in,
                              void* d_out, int out_size) {
    const float* x       = (const float*)d_in[0];
    const int*   ei      = (const int*)d_in[1];
    const float* W1      = (const float*)d_in[2];
    const float* b1      = (const float*)d_in[3];
    const float* W2      = (const float*)d_in[4];
    const float* b2      = (const float*)d_in[5];
    const float* W3      = (const float*)d_in[6];
    const float* b3      = (const float*)d_in[7];
    const float* Wg      = (const float*)d_in[8];
    const float* att_src = (const float*)d_in[9];
    const float* att_dst = (const float*)d_in[10];
    const float* bg      = (const float*)d_in[11];
    const float* Wl      = (const float*)d_in[12];
    const float* bl      = (const float*)d_in[13];
    float* out = (float*)d_out;

    const int* src = ei;
    const int* dst = ei + N_EDGES;

    float *pA, *pB, *pC, *pD, *pAS, *pAD, *pDinv;
    int *pDeg, *pRow, *pCur, *pCol, *pBsum;
    cudaGetSymbolAddress((void**)&pA, g_bufA);
    cudaGetSymbolAddress((void**)&pB, g_bufB);
    cudaGetSymbolAddress((void**)&pC, g_bufC);
    cudaGetSymbolAddress((void**)&pD, g_bufD);
    cudaGetSymbolAddress((void**)&pAS, g_as);
    cudaGetSymbolAddress((void**)&pAD, g_ad);
    cudaGetSymbolAddress((void**)&pDinv, g_dinv);
    cudaGetSymbolAddress((void**)&pDeg, g_deg);
    cudaGetSymbolAddress((void**)&pRow, g_rowptr);
    cudaGetSymbolAddress((void**)&pCur, g_cur);
    cudaGetSymbolAddress((void**)&pCol, g_col);
    cudaGetSymbolAddress((void**)&pBsum, g_bsum);

    const int TB = 256;
    const int gN = (N_NODES + TB - 1) / TB;
    const int gE = (N_EDGES + TB - 1) / TB;
    const int gW = (N_NODES + 7) / 8;     // warp-per-node, 8 warps/block
    const int gF = N_NODES / 32;          // fused transform: 32 nodes/block (3125)

    // ---- build CSR ----
    cudaMemsetAsync(pDeg, 0, N_NODES * sizeof(int));
    hist_kernel<<<gE, TB>>>(dst, pDeg, N_EDGES);
    scan1_kernel<<<NB_SCAN, 1024>>>(pDeg, pRow, pBsum, N_NODES);
    scan2_kernel<<<1, 128>>>(pBsum, NB_SCAN);
    csr_init_kernel<<<gN, TB>>>(pRow, pBsum, pDeg, pCur, pCol, pDinv, N_NODES);
    fill_kernel<<<gE, TB>>>(src, dst, pCur, pCol, N_EDGES);

    // ---- layer 1: GCN 128->32 ----
    gemm_l1_kernel<<<gW, TB>>>(x, W1, pDinv, pA, N_NODES);                 // t0
    agg32_kernel<0><<<gW, TB>>>(pA, pRow, pCol, pDinv, b1, pB, N_NODES);   // t1 = h1*dinv

    // ---- layer 2 aggregate (32ch) then fused GEMMs (g3 -> half) ----
    agg32_kernel<1><<<gW, TB>>>(pB, pRow, pCol, pDinv, nullptr, pA, N_NODES);  // z2
    fused_transform_kernel<32, false><<<gF, TB>>>(pA, nullptr, W2, b2, Wg,
                                                  att_src, att_dst,
                                                  (__half2*)pC, pAS, pAD);

    // ---- layer 3: GAT aggregate (half g3) -> h3 fp32 (pD), t3 half (pB) ----
    gat_agg_kernel<false><<<gW, TB>>>((const __half*)pC, pAS, pAD, pRow, pCol, bg, pDinv,
                                      pD, (__half2*)pB, nullptr, nullptr, nullptr, N_NODES);

    // ---- layer 4 aggregate (half t3) then fused GEMMs (residual, g5 half) ----
    agg64h_kernel<<<gW, TB>>>((const __half*)pB, pRow, pCol, pDinv, pA, N_NODES);  // z4
    fused_transform_kernel<64, true><<<gF, TB>>>(pA, pD, W3, b3, Wg,
                                                 att_src, att_dst,
                                                 (__half2*)pC, pAS, pAD);

    // ---- layer 5: GAT aggregate (half g5) + final projection ----
    gat_agg_kernel<true><<<gW, TB>>>((const __half*)pC, pAS, pAD, pRow, pCol, bg, pDinv,
                                     nullptr, nullptr, Wl, bl, out, N_NODES);
}

// round 17
// speedup vs baseline: 1.9824x; 1.0106x over previous
#include <cuda_runtime.h>
#include <cuda_fp16.h>
#include <cstdint>

#define N_NODES 100000
#define N_EDGES 1600000
#define E_TOTAL (N_EDGES + N_NODES)   // 1,700,000
#define NB_SCAN ((N_NODES + 1023) / 1024)   // 98

// ---------------------------------------------------------------------------
// Scratch (device globals -- no allocation allowed)
// ---------------------------------------------------------------------------
__device__ int   g_deg[N_NODES];
__device__ int   g_rowptr[N_NODES + 1];
__device__ int   g_cur[N_NODES];
__device__ int   g_col[E_TOTAL];
__device__ int   g_bsum[128];
__device__ float g_dinv[N_NODES];
__device__ float g_bufA[(size_t)N_NODES * 64];
__device__ float g_bufB[(size_t)N_NODES * 64];
__device__ float g_bufC[(size_t)N_NODES * 64];
__device__ float g_bufD[(size_t)N_NODES * 64];
__device__ float g_as[(size_t)N_NODES * 4];
__device__ float g_ad[(size_t)N_NODES * 4];

__device__ __forceinline__ float lrelu(float x) { return x > 0.f ? x : 0.2f * x; }

union F2U { float2 f; unsigned long long u; };
__device__ __forceinline__ float2 ffma2(float2 a, float2 b, float2 c) {
    F2U ua, ub, uc; ua.f = a; ub.f = b; uc.f = c;
    asm("fma.rn.f32x2 %0, %1, %2, %0;" : "+l"(uc.u) : "l"(ua.u), "l"(ub.u));
    return uc.f;
}

// ---------------------------------------------------------------------------
// CSR build (deg zeroed by cudaMemsetAsync; self-loop +1 folded into scan)
// ---------------------------------------------------------------------------
__global__ void hist_kernel(const int* __restrict__ dst, int* __restrict__ deg, int e) {
    int i = blockIdx.x * blockDim.x + threadIdx.x;
    if (i < e) atomicAdd(&deg[dst[i]], 1);
}

__global__ void scan1_kernel(const int* __restrict__ deg, int* __restrict__ part,
                             int* __restrict__ bsum, int n) {
    __shared__ int ws[32];
    int tid = threadIdx.x, lane = tid & 31, wid = tid >> 5;
    int i = blockIdx.x * 1024 + tid;
    int v = (i < n) ? deg[i] + 1 : 0;   // +1 = self loop
    int x = v;
#pragma unroll
    for (int o = 1; o < 32; o <<= 1) {
        int t = __shfl_up_sync(0xffffffffu, x, o);
        if (lane >= o) x += t;
    }
    if (lane == 31) ws[wid] = x;
    __syncthreads();
    if (wid == 0) {
        int s = ws[lane];
        int y = s;
#pragma unroll
        for (int o = 1; o < 32; o <<= 1) {
            int t = __shfl_up_sync(0xffffffffu, y, o);
            if (lane >= o) y += t;
        }
        ws[lane] = y - s;
        if (lane == 31) bsum[blockIdx.x] = y;
    }
    __syncthreads();
    if (i < n) part[i] = x - v + ws[wid];
}

__global__ void scan2_kernel(int* bsum, int nb) {
    __shared__ int ws[4];
    int tid = threadIdx.x, lane = tid & 31, wid = tid >> 5;
    int v = (tid < nb) ? bsum[tid] : 0;
    int x = v;
#pragma unroll
    for (int o = 1; o < 32; o <<= 1) {
        int t = __shfl_up_sync(0xffffffffu, x, o);
        if (lane >= o) x += t;
    }
    if (lane == 31) ws[wid] = x;
    __syncthreads();
    int off = 0;
    for (int w = 0; w < wid; w++) off += ws[w];
    if (tid < nb) bsum[tid] = x - v + off;
}

__global__ void csr_init_kernel(int* __restrict__ rowptr, const int* __restrict__ bsum,
                                const int* __restrict__ deg, int* __restrict__ cur,
                                int* __restrict__ col, float* __restrict__ dinv, int n) {
    int i = blockIdx.x * blockDim.x + threadIdx.x;
    if (i >= n) return;
    int r = rowptr[i] + bsum[i >> 10];
    rowptr[i] = r;
    col[r] = i;          // self loop in slot 0
    cur[i] = r + 1;
    dinv[i] = rsqrtf((float)(deg[i] + 1));
    if (i == 0) rowptr[n] = E_TOTAL;
}

__global__ void fill_kernel(const int* __restrict__ src, const int* __restrict__ dst,
                            int* __restrict__ cur, int* __restrict__ col, int e) {
    int i = blockIdx.x * blockDim.x + threadIdx.x;
    if (i >= e) return;
    int p = atomicAdd(&cur[dst[i]], 1);
    col[p] = src[i];
}

// ---------------------------------------------------------------------------
// Layer-1 GEMM: t0 = (x @ W1) * dinv   (128 -> 32), OUTPUT HALF
// lane pair-packing via shfl: even lanes store half2 (channels lane, lane+1)
// ---------------------------------------------------------------------------
__global__ void gemm_l1_kernel(const float* __restrict__ in, const float* __restrict__ W,
                               const float* __restrict__ dinv, __half2* __restrict__ out,
                               int n_nodes) {
    __shared__ float Wsh[128 * 32];
    int tid = threadIdx.x;
    for (int i = tid; i < 128 * 32; i += blockDim.x) Wsh[i] = W[i];
    __syncthreads();
    int warp = tid >> 5, lane = tid & 31;
    int n = blockIdx.x * (blockDim.x >> 5) + warp;
    if (n >= n_nodes) return;
    const float4* xr = reinterpret_cast<const float4*>(in + (size_t)n * 128);
    float acc = 0.f;
#pragma unroll
    for (int k4 = 0; k4 < 32; k4++) {
        float4 x4 = __ldg(xr + k4);
        acc += x4.x * Wsh[(4 * k4 + 0) * 32 + lane];
        acc += x4.y * Wsh[(4 * k4 + 1) * 32 + lane];
        acc += x4.z * Wsh[(4 * k4 + 2) * 32 + lane];
        acc += x4.w * Wsh[(4 * k4 + 3) * 32 + lane];
    }
    acc *= dinv[n];
    float nb = __shfl_down_sync(0xffffffffu, acc, 1);
    if ((lane & 1) == 0)
        out[(size_t)n * 16 + (lane >> 1)] = __floats2half2_rn(acc, nb);
}

// ---------------------------------------------------------------------------
// 32-channel GCN aggregation from HALF input: quarter-warp, uint2 (4 half)
// per lane, 4 edges in flight/iter.
// MODE 0: out = relu(dinv*acc + b) * dinv  -> HALF (t1)
// MODE 1: out = dinv*acc                   -> FP32 (z2 for FFMA2 transform)
// ---------------------------------------------------------------------------
template <int MODE>
__global__ void agg32_kernel(const __half* __restrict__ t, const int* __restrict__ rowptr,
                             const int* __restrict__ col, const float* __restrict__ dinv,
                             const float* __restrict__ bias, void* __restrict__ out,
                             int n_nodes) {
    int warp = (blockIdx.x * blockDim.x + threadIdx.x) >> 5;
    if (warp >= n_nodes) return;
    int lane = threadIdx.x & 31;
    int q = lane >> 3, l8 = lane & 7;
    int beg = rowptr[warp], end = rowptr[warp + 1];
    float ax = 0.f, ay = 0.f, az = 0.f, aw = 0.f;
#pragma unroll 4
    for (int i = beg + q; i < end; i += 4) {
        int s = __ldg(&col[i]);
        uint2 raw = *reinterpret_cast<const uint2*>(t + (size_t)s * 32 + 4 * l8);
        float2 f0 = __half22float2(*reinterpret_cast<__half2*>(&raw.x));
        float2 f1 = __half22float2(*reinterpret_cast<__half2*>(&raw.y));
        ax += f0.x; ay += f0.y; az += f1.x; aw += f1.y;
    }
#pragma unroll
    for (int o = 8; o <= 16; o <<= 1) {
        ax += __shfl_xor_sync(0xffffffffu, ax, o);
        ay += __shfl_xor_sync(0xffffffffu, ay, o);
        az += __shfl_xor_sync(0xffffffffu, az, o);
        aw += __shfl_xor_sync(0xffffffffu, aw, o);
    }
    float dn = dinv[warp];
    if (MODE == 0) {
        float4 bv = __ldg(reinterpret_cast<const float4*>(&bias[4 * l8]));
        ax = fmaxf(dn * ax + bv.x, 0.f) * dn;
        ay = fmaxf(dn * ay + bv.y, 0.f) * dn;
        az = fmaxf(dn * az + bv.z, 0.f) * dn;
        aw = fmaxf(dn * aw + bv.w, 0.f) * dn;
        if (lane < 8) {
            uint2 pk;
            __half2 p0 = __floats2half2_rn(ax, ay);
            __half2 p1 = __floats2half2_rn(az, aw);
            pk.x = *reinterpret_cast<unsigned*>(&p0);
            pk.y = *reinterpret_cast<unsigned*>(&p1);
            *reinterpret_cast<uint2*>((__half*)out + (size_t)warp * 32 + 4 * l8) = pk;
        }
    } else {
        if (lane < 8) {
            *reinterpret_cast<float4*>((float*)out + (size_t)warp * 32 + 4 * l8) =
                make_float4(ax * dn, ay * dn, az * dn, aw * dn);
        }
    }
}

// ---------------------------------------------------------------------------
// 64-channel GCN pre-aggregate from HALF input: z = dinv * sum t[s] (layer 4)
// ---------------------------------------------------------------------------
__global__ void agg64h_kernel(const __half* __restrict__ t, const int* __restrict__ rowptr,
                              const int* __restrict__ col, const float* __restrict__ dinv,
                              float* __restrict__ out, int n_nodes) {
    int warp = (blockIdx.x * blockDim.x + threadIdx.x) >> 5;
    if (warp >= n_nodes) return;
    int lane = threadIdx.x & 31;
    int h = lane >> 4, l16 = lane & 15;
    int beg = rowptr[warp], end = rowptr[warp + 1];
    float ax = 0.f, ay = 0.f, az = 0.f, aw = 0.f;
#pragma unroll 4
    for (int i = beg + h; i < end; i += 2) {
        int s = __ldg(&col[i]);
        uint2 raw = *reinterpret_cast<const uint2*>(t + (size_t)s * 64 + 4 * l16);
        float2 f0 = __half22float2(*reinterpret_cast<__half2*>(&raw.x));
        float2 f1 = __half22float2(*reinterpret_cast<__half2*>(&raw.y));
        ax += f0.x; ay += f0.y; az += f1.x; aw += f1.y;
    }
    ax += __shfl_xor_sync(0xffffffffu, ax, 16);
    ay += __shfl_xor_sync(0xffffffffu, ay, 16);
    az += __shfl_xor_sync(0xffffffffu, az, 16);
    aw += __shfl_xor_sync(0xffffffffu, aw, 16);
    float dn = dinv[warp];
    if (lane < 16) {
        *reinterpret_cast<float4*>(&out[(size_t)warp * 64 + 4 * l16]) =
            make_float4(ax * dn, ay * dn, az * dn, aw * dn);
    }
}

// ---------------------------------------------------------------------------
// Fused transform: h = relu(z @ Wa + ba) [+ hres]; g = h @ Wg; GAT scores.
// g emitted as __half2; scores from fp32 accumulators.
// ---------------------------------------------------------------------------
template <int CIN, bool RESID>
__global__ __launch_bounds__(256) void fused_transform_kernel(
    const float* __restrict__ z, const float* __restrict__ hres,
    const float* __restrict__ Wa, const float* __restrict__ ba,
    const float* __restrict__ Wg, const float* __restrict__ att_s,
    const float* __restrict__ att_d, __half2* __restrict__ gout,
    float* __restrict__ a_s, float* __restrict__ a_d) {
    __shared__ float Was[CIN * 64];
    __shared__ float Wgs[64 * 64];
    __shared__ float Hs[8][256];
    int tid = threadIdx.x;
    for (int i = tid; i < CIN * 64; i += 256) Was[i] = Wa[i];
    for (int i = tid; i < 64 * 64; i += 256) Wgs[i] = Wg[i];
    __syncthreads();
    int warp = tid >> 5, lane = tid & 31;
    int node0 = blockIdx.x * 32 + warp * 4;

    float2 acc[4];
#pragma unroll
    for (int j = 0; j < 4; j++) acc[j] = make_float2(0.f, 0.f);
    for (int k = 0; k < CIN; k += 4) {
        float2 w0 = *reinterpret_cast<const float2*>(&Was[(k + 0) * 64 + 2 * lane]);
        float2 w1 = *reinterpret_cast<const float2*>(&Was[(k + 1) * 64 + 2 * lane]);
        float2 w2 = *reinterpret_cast<const float2*>(&Was[(k + 2) * 64 + 2 * lane]);
        float2 w3 = *reinterpret_cast<const float2*>(&Was[(k + 3) * 64 + 2 * lane]);
#pragma unroll
        for (int j = 0; j < 4; j++) {
            float4 xv = __ldg(reinterpret_cast<const float4*>(&z[(size_t)(node0 + j) * CIN + k]));
            acc[j] = ffma2(make_float2(xv.x, xv.x), w0, acc[j]);
            acc[j] = ffma2(make_float2(xv.y, xv.y), w1, acc[j]);
            acc[j] = ffma2(make_float2(xv.z, xv.z), w2, acc[j]);
            acc[j] = ffma2(make_float2(xv.w, xv.w), w3, acc[j]);
        }
    }
    float2 bv = __ldg(reinterpret_cast<const float2*>(&ba[2 * lane]));
#pragma unroll
    for (int j = 0; j < 4; j++) {
        float hx = fmaxf(acc[j].x + bv.x, 0.f);
        float hy = fmaxf(acc[j].y + bv.y, 0.f);
        if (RESID) {
            float2 rr = *reinterpret_cast<const float2*>(&hres[(size_t)(node0 + j) * 64 + 2 * lane]);
            hx += rr.x; hy += rr.y;
        }
        *reinterpret_cast<float2*>(&Hs[warp][j * 64 + 2 * lane]) = make_float2(hx, hy);
    }
    __syncwarp();

#pragma unroll
    for (int j = 0; j < 4; j++) acc[j] = make_float2(0.f, 0.f);
    for (int k = 0; k < 64; k += 4) {
        float2 w0 = *reinterpret_cast<const float2*>(&Wgs[(k + 0) * 64 + 2 * lane]);
        float2 w1 = *reinterpret_cast<const float2*>(&Wgs[(k + 1) * 64 + 2 * lane]);
        float2 w2 = *reinterpret_cast<const float2*>(&Wgs[(k + 2) * 64 + 2 * lane]);
        float2 w3 = *reinterpret_cast<const float2*>(&Wgs[(k + 3) * 64 + 2 * lane]);
#pragma unroll
        for (int j = 0; j < 4; j++) {
            float4 hv = *reinterpret_cast<const float4*>(&Hs[warp][j * 64 + k]);
            acc[j] = ffma2(make_float2(hv.x, hv.x), w0, acc[j]);
            acc[j] = ffma2(make_float2(hv.y, hv.y), w1, acc[j]);
            acc[j] = ffma2(make_float2(hv.z, hv.z), w2, acc[j]);
            acc[j] = ffma2(make_float2(hv.w, hv.w), w3, acc[j]);
        }
    }
    float ats0 = __ldg(&att_s[2 * lane]), ats1 = __ldg(&att_s[2 * lane + 1]);
    float atd0 = __ldg(&att_d[2 * lane]), atd1 = __ldg(&att_d[2 * lane + 1]);
#pragma unroll
    for (int j = 0; j < 4; j++) {
        int n = node0 + j;
        float gx = acc[j].x, gy = acc[j].y;
        gout[(size_t)n * 32 + lane] = __floats2half2_rn(gx, gy);
        float ps = gx * ats0 + gy * ats1;
        float pd = gx * atd0 + gy * atd1;
#pragma unroll
        for (int o = 1; o < 8; o <<= 1) {
            ps += __shfl_xor_sync(0xffffffffu, ps, o);
            pd += __shfl_xor_sync(0xffffffffu, pd, o);
        }
        if ((lane & 7) == 0) {
            a_s[(size_t)n * 4 + (lane >> 3)] = ps;
            a_d[(size_t)n * 4 + (lane >> 3)] = pd;
        }
    }
}

// ---------------------------------------------------------------------------
// GAT aggregation, no-max softmax, half feature payload.
// FINAL=false: out1 = relu(agg+bias) fp32 (residual), out2 = out1*dinv HALF
// FINAL=true : fout[n] = relu(<relu(agg+bias), Wl> + bl)
// ---------------------------------------------------------------------------
#define GAT_CAP 128

template <bool FINAL>
__global__ __launch_bounds__(256) void gat_agg_kernel(
    const __half* __restrict__ gh, const float* __restrict__ a_s,
    const float* __restrict__ a_d, const int* __restrict__ rowptr,
    const int* __restrict__ col, const float* __restrict__ bias,
    const float* __restrict__ dinv, float* __restrict__ out1,
    __half2* __restrict__ out2, const float* __restrict__ Wl,
    const float* __restrict__ bl, float* __restrict__ fout, int n_nodes) {
    __shared__ float ex_sh[8][GAT_CAP * 4];   // 16 KB
    __shared__ int   col_sh[8][GAT_CAP];      //  4 KB
    int gwarp = (blockIdx.x * blockDim.x + threadIdx.x) >> 5;
    if (gwarp >= n_nodes) return;
    int warp = threadIdx.x >> 5, lane = threadIdx.x & 31;
    int n = gwarp;
    int beg = rowptr[n], end = rowptr[n + 1];
    int deg = end - beg;
    float4 ad4 = *reinterpret_cast<const float4*>(&a_d[(size_t)n * 4]);

    if (deg <= GAT_CAP) {
        float d0 = 0.f, d1 = 0.f, d2 = 0.f, d3 = 0.f;
        for (int i = lane; i < deg; i += 32) {
            int s = __ldg(&col[beg + i]);
            col_sh[warp][i] = s;
            float4 as4 = __ldg(reinterpret_cast<const float4*>(&a_s[(size_t)s * 4]));
            float x0 = __expf(lrelu(as4.x + ad4.x));
            float x1 = __expf(lrelu(as4.y + ad4.y));
            float x2 = __expf(lrelu(as4.z + ad4.z));
            float x3 = __expf(lrelu(as4.w + ad4.w));
            *reinterpret_cast<float4*>(&ex_sh[warp][i * 4]) = make_float4(x0, x1, x2, x3);
            d0 += x0; d1 += x1; d2 += x2; d3 += x3;
        }
#pragma unroll
        for (int o = 16; o; o >>= 1) {
            d0 += __shfl_xor_sync(0xffffffffu, d0, o);
            d1 += __shfl_xor_sync(0xffffffffu, d1, o);
            d2 += __shfl_xor_sync(0xffffffffu, d2, o);
            d3 += __shfl_xor_sync(0xffffffffu, d3, o);
        }
        int hh = lane >> 4, l16 = lane & 15;
        int head = l16 >> 2;
        float dh = (head == 0) ? d0 : (head == 1) ? d1 : (head == 2) ? d2 : d3;
        float rh = 1.f / (dh + 1e-16f);
        __syncwarp();
        float ax = 0.f, ay = 0.f, az = 0.f, aw = 0.f;
#pragma unroll 4
        for (int i = hh; i < deg; i += 2) {
            int s = col_sh[warp][i];
            float al = ex_sh[warp][i * 4 + head] * rh;
            uint2 raw = *reinterpret_cast<const uint2*>(gh + (size_t)s * 64 + 4 * l16);
            float2 f0 = __half22float2(*reinterpret_cast<__half2*>(&raw.x));
            float2 f1 = __half22float2(*reinterpret_cast<__half2*>(&raw.y));
            ax += al * f0.x; ay += al * f0.y; az += al * f1.x; aw += al * f1.y;
        }
        ax += __shfl_xor_sync(0xffffffffu, ax, 16);
        ay += __shfl_xor_sync(0xffffffffu, ay, 16);
        az += __shfl_xor_sync(0xffffffffu, az, 16);
        aw += __shfl_xor_sync(0xffffffffu, aw, 16);

        float4 b4 = __ldg(reinterpret_cast<const float4*>(&bias[4 * l16]));
        float h0 = fmaxf(ax + b4.x, 0.f);
        float h1 = fmaxf(ay + b4.y, 0.f);
        float h2 = fmaxf(az + b4.z, 0.f);
        float h3 = fmaxf(aw + b4.w, 0.f);
        if (!FINAL) {
            if (lane < 16) {
                *reinterpret_cast<float4*>(&out1[(size_t)n * 64 + 4 * l16]) =
                    make_float4(h0, h1, h2, h3);
                float dn = dinv[n];
                uint2 pk;
                __half2 p0 = __floats2half2_rn(h0 * dn, h1 * dn);
                __half2 p1 = __floats2half2_rn(h2 * dn, h3 * dn);
                pk.x = *reinterpret_cast<unsigned*>(&p0);
                pk.y = *reinterpret_cast<unsigned*>(&p1);
                *reinterpret_cast<uint2*>(&out2[(size_t)n * 32 + 2 * l16]) = pk;
            }
        } else {
            float4 w4 = __ldg(reinterpret_cast<const float4*>(&Wl[4 * l16]));
            float p = h0 * w4.x + h1 * w4.y + h2 * w4.z + h3 * w4.w;
#pragma unroll
            for (int o = 8; o; o >>= 1) p += __shfl_xor_sync(0xffffffffu, p, o);
            if (lane == 0) fout[n] = fmaxf(p + __ldg(bl), 0.f);
        }
    } else {
        // fallback for degree > 128 (rare): 2-pass global, no max
        float d0 = 0.f, d1 = 0.f, d2 = 0.f, d3 = 0.f;
        for (int i = beg + lane; i < end; i += 32) {
            int s = __ldg(&col[i]);
            float4 as4 = __ldg(reinterpret_cast<const float4*>(&a_s[(size_t)s * 4]));
            d0 += __expf(lrelu(as4.x + ad4.x));
            d1 += __expf(lrelu(as4.y + ad4.y));
            d2 += __expf(lrelu(as4.z + ad4.z));
            d3 += __expf(lrelu(as4.w + ad4.w));
        }
#pragma unroll
        for (int o = 16; o; o >>= 1) {
            d0 += __shfl_xor_sync(0xffffffffu, d0, o);
            d1 += __shfl_xor_sync(0xffffffffu, d1, o);
            d2 += __shfl_xor_sync(0xffffffffu, d2, o);
            d3 += __shfl_xor_sync(0xffffffffu, d3, o);
        }
        float r0 = 1.f / (d0 + 1e-16f), r1 = 1.f / (d1 + 1e-16f);
        float r2 = 1.f / (d2 + 1e-16f), r3 = 1.f / (d3 + 1e-16f);
        int h = lane & 3;
        float adh = (h == 0) ? ad4.x : (h == 1) ? ad4.y : (h == 2) ? ad4.z : ad4.w;
        float rh  = (h == 0) ? r0 : (h == 1) ? r1 : (h == 2) ? r2 : r3;
        int hsel = lane >> 3;
        float ax = 0.f, ay = 0.f;
        for (int i = beg; i < end; i++) {
            int s = __ldg(&col[i]);
            float asv = __ldg(&a_s[(size_t)s * 4 + h]);
            float al = __expf(lrelu(asv + adh)) * rh;
            float alpha = __shfl_sync(0xffffffffu, al, hsel);
            float2 f = __half22float2(
                *reinterpret_cast<const __half2*>(gh + (size_t)s * 64 + 2 * lane));
            ax += alpha * f.x;
            ay += alpha * f.y;
        }
        float2 b2 = __ldg(reinterpret_cast<const float2*>(&bias[2 * lane]));
        float hx = fmaxf(ax + b2.x, 0.f);
        float hy = fmaxf(ay + b2.y, 0.f);
        if (!FINAL) {
            *reinterpret_cast<float2*>(&out1[(size_t)n * 64 + 2 * lane]) = make_float2(hx, hy);
            float dn = dinv[n];
            out2[(size_t)n * 32 + lane] = __floats2half2_rn(hx * dn, hy * dn);
        } else {
            float2 w = __ldg(reinterpret_cast<const float2*>(&Wl[2 * lane]));
            float p = hx * w.x + hy * w.y;
#pragma unroll
            for (int o = 16; o; o >>= 1) p += __shfl_xor_sync(0xffffffffu, p, o);
            if (lane == 0) fout[n] = fmaxf(p + __ldg(bl), 0.f);
        }
    }
}

// ---------------------------------------------------------------------------
// Launch
// ---------------------------------------------------------------------------
extern "C" void kernel_launch(void* const* d_in, const int* in_sizes, int n_in,
                              void* d_out, int out_size) {
    const float* x       = (const float*)d_in[0];
    const int*   ei      = (const int*)d_in[1];
    const float* W1      = (const float*)d_in[2];
    const float* b1      = (const float*)d_in[3];
    const float* W2      = (const float*)d_in[4];
    const float* b2      = (const float*)d_in[5];
    const float* W3      = (const float*)d_in[6];
    const float* b3      = (const float*)d_in[7];
    const float* Wg      = (const float*)d_in[8];
    const float* att_src = (const float*)d_in[9];
    const float* att_dst = (const float*)d_in[10];
    const float* bg      = (const float*)d_in[11];
    const float* Wl      = (const float*)d_in[12];
    const float* bl      = (const float*)d_in[13];
    float* out = (float*)d_out;

    const int* src = ei;
    const int* dst = ei + N_EDGES;

    float *pA, *pB, *pC, *pD, *pAS, *pAD, *pDinv;
    int *pDeg, *pRow, *pCur, *pCol, *pBsum;
    cudaGetSymbolAddress((void**)&pA, g_bufA);
    cudaGetSymbolAddress((void**)&pB, g_bufB);
    cudaGetSymbolAddress((void**)&pC, g_bufC);
    cudaGetSymbolAddress((void**)&pD, g_bufD);
    cudaGetSymbolAddress((void**)&pAS, g_as);
    cudaGetSymbolAddress((void**)&pAD, g_ad);
    cudaGetSymbolAddress((void**)&pDinv, g_dinv);
    cudaGetSymbolAddress((void**)&pDeg, g_deg);
    cudaGetSymbolAddress((void**)&pRow, g_rowptr);
    cudaGetSymbolAddress((void**)&pCur, g_cur);
    cudaGetSymbolAddress((void**)&pCol, g_col);
    cudaGetSymbolAddress((void**)&pBsum, g_bsum);

    const int TB = 256;
    const int gN = (N_NODES + TB - 1) / TB;
    const int gE = (N_EDGES + TB - 1) / TB;
    const int gW = (N_NODES + 7) / 8;     // warp-per-node, 8 warps/block
    const int gF = N_NODES / 32;          // fused transform: 32 nodes/block (3125)

    // ---- build CSR ----
    cudaMemsetAsync(pDeg, 0, N_NODES * sizeof(int));
    hist_kernel<<<gE, TB>>>(dst, pDeg, N_EDGES);
    scan1_kernel<<<NB_SCAN, 1024>>>(pDeg, pRow, pBsum, N_NODES);
    scan2_kernel<<<1, 128>>>(pBsum, NB_SCAN);
    csr_init_kernel<<<gN, TB>>>(pRow, pBsum, pDeg, pCur, pCol, pDinv, N_NODES);
    fill_kernel<<<gE, TB>>>(src, dst, pCur, pCol, N_EDGES);

    // ---- layer 1: GCN 128->32 (t0 half) ----
    gemm_l1_kernel<<<gW, TB>>>(x, W1, pDinv, (__half2*)pA, N_NODES);
    agg32_kernel<0><<<gW, TB>>>((const __half*)pA, pRow, pCol, pDinv, b1, pB, N_NODES);  // t1 half

    // ---- layer 2 aggregate (32ch half) then fused GEMMs (g3 -> half) ----
    agg32_kernel<1><<<gW, TB>>>((const __half*)pB, pRow, pCol, pDinv, nullptr, pA, N_NODES);  // z2 fp32
    fused_transform_kernel<32, false><<<gF, TB>>>(pA, nullptr, W2, b2, Wg,
                                                  att_src, att_dst,
                                                  (__half2*)pC, pAS, pAD);

    // ---- layer 3: GAT aggregate (half g3) -> h3 fp32 (pD), t3 half (pB) ----
    gat_agg_kernel<false><<<gW, TB>>>((const __half*)pC, pAS, pAD, pRow, pCol, bg, pDinv,
                                      pD, (__half2*)pB, nullptr, nullptr, nullptr, N_NODES);

    // ---- layer 4 aggregate (half t3) then fused GEMMs (residual, g5 half) ----
    agg64h_kernel<<<gW, TB>>>((const __half*)pB, pRow, pCol, pDinv, pA, N_NODES);  // z4
    fused_transform_kernel<64, true><<<gF, TB>>>(pA, pD, W3, b3, Wg,
                                                 att_src, att_dst,
                                                 (__half2*)pC, pAS, pAD);

    // ---- layer 5: GAT aggregate (half g5) + final projection ----
    gat_agg_kernel<true><<<gW, TB>>>((const __half*)pC, pAS, pAD, pRow, pCol, bg, pDinv,
                                     nullptr, nullptr, Wl, bl, out, N_NODES);
}